// round 13
// baseline (speedup 1.0000x reference)
#include <cuda_runtime.h>
#include <cuda_fp16.h>
#include <cstdint>

// ---------------------------------------------------------------------------
// Neural-SDF ray march + tube min + reflectance.
// Warp-cooperative, 32 rays/warp; each SDF eval = 32x128x128 GEMM via
// mma.sync.m16n8k16 f16 (256 mma). Half-split layer-2 (C=64 regs) with
// layer-1 RECOMPUTED per half using packed fp32 FMA (fma.rn.f32x2) so no
// persistent A registers -> fits __launch_bounds__(128,4) = 16 warps/SM.
//   * march + tube scan: 1-term fp16
//   * column-3: ONE precise 3-term eval per ray at the approx argmin;
//     B_lo residuals streamed from a __device__ global (L2-resident)
// ---------------------------------------------------------------------------

#define DINL __device__ __forceinline__

namespace {
constexpr int   HN     = 128;
constexpr float kNEAR  = 0.2f;
constexpr float kFAR   = 2.0f;
constexpr float kALPHA = 100.0f;
constexpr float kEPS   = 0.005f;
constexpr int   kITERS = 32;
constexpr int   kTP    = 32;
constexpr float kSTEP  = 0.0634765625f;  // (2 + 0.5*(2/32))/32, exact fp32

// shared memory layout (float offsets)
constexpr int OFF_BH   = 0;        // 8192: W2 fp16-hi frag pack (float4 = 2 nb)
constexpr int OFF_W1D  = 8192;     // 1024: W1 duplicated pairs per j:
                                   //   {wx,wx,wy,wy,wz,wz,b1,b1}
constexpr int OFF_W1   = 9216;     // float4[128]: (W1[0][k],W1[1][k],W1[2][k],b1[k])
constexpr int OFF_BW   = 9728;     // float2[128]: (b2[n], W3[n])
constexpr int OFF_R1A  = 9984;     // float4[128]: R1 rows 0..3
constexpr int OFF_R1B  = 10496;    // float4[128]: (R1[4][j],R1[5][j],rb1[j],0)
constexpr int OFF_R2   = 11008;    // float4[128]: (R2[j][0..2],0)
constexpr int OFF_MISC = 11520;    // rb2[0..2], b3
constexpr int SMEM_FLOATS = 11524;
constexpr int SMEM_BYTES  = SMEM_FLOATS * 4;
}  // namespace

// W2 fp16 residuals in mma-fragment pack (precise eval only; L2-resident).
__device__ float4 g_BL[2048];

// ----------------------------- helpers --------------------------------------
DINL uint32_t pk16(float e0, float e1) {
    uint32_t d;
    asm("cvt.rn.f16x2.f32 %0, %1, %2;" : "=r"(d) : "f"(e1), "f"(e0));
    return d;
}
DINL uint32_t pk16relu(float e0, float e1) {
    uint32_t d;
    asm("cvt.rn.relu.f16x2.f32 %0, %1, %2;" : "=r"(d) : "f"(e1), "f"(e0));
    return d;
}
DINL float f16_round(float x) { return __half2float(__float2half_rn(x)); }

DINL unsigned long long pkf2(float a, float b) {
    unsigned long long d;
    asm("mov.b64 %0, {%1, %2};" : "=l"(d) : "f"(a), "f"(b));
    return d;
}
DINL float2 unpk(unsigned long long v) {
    float2 r;
    asm("mov.b64 {%0, %1}, %2;" : "=f"(r.x), "=f"(r.y) : "l"(v));
    return r;
}
DINL unsigned long long fma2_(unsigned long long a, unsigned long long b,
                              unsigned long long c) {
    unsigned long long d;
    asm("fma.rn.f32x2 %0, %1, %2, %3;" : "=l"(d) : "l"(a), "l"(b), "l"(c));
    return d;
}

DINL void mma16_acc(float c[4], uint32_t a0, uint32_t a1, uint32_t a2,
                    uint32_t a3, uint32_t b0, uint32_t b1) {
    asm volatile(
        "mma.sync.aligned.m16n8k16.row.col.f32.f16.f16.f32 "
        "{%0,%1,%2,%3},{%4,%5,%6,%7},{%8,%9},{%0,%1,%2,%3};"
        : "+f"(c[0]), "+f"(c[1]), "+f"(c[2]), "+f"(c[3])
        : "r"(a0), "r"(a1), "r"(a2), "r"(a3), "r"(b0), "r"(b1));
}
DINL void mma16_zero(float c[4], uint32_t a0, uint32_t a1, uint32_t a2,
                     uint32_t a3, uint32_t b0, uint32_t b1) {
    float z = 0.0f;
    asm volatile(
        "mma.sync.aligned.m16n8k16.row.col.f32.f16.f16.f32 "
        "{%0,%1,%2,%3},{%4,%5,%6,%7},{%8,%9},{%10,%10,%10,%10};"
        : "=f"(c[0]), "=f"(c[1]), "=f"(c[2]), "=f"(c[3])
        : "r"(a0), "r"(a1), "r"(a2), "r"(a3), "r"(b0), "r"(b1), "f"(z));
}

// lane 4g+c exposes ray g+8c; owner lane l fetches from 4*(l&7)+(l>>3)
DINL float expose_own(float p0, float p1, float p2, float p3, int lane) {
    p0 += __shfl_xor_sync(0xffffffffu, p0, 1);
    p0 += __shfl_xor_sync(0xffffffffu, p0, 2);
    p1 += __shfl_xor_sync(0xffffffffu, p1, 1);
    p1 += __shfl_xor_sync(0xffffffffu, p1, 2);
    p2 += __shfl_xor_sync(0xffffffffu, p2, 1);
    p2 += __shfl_xor_sync(0xffffffffu, p2, 2);
    p3 += __shfl_xor_sync(0xffffffffu, p3, 1);
    p3 += __shfl_xor_sync(0xffffffffu, p3, 2);
    const int t4 = lane & 3;
    float expose = (t4 == 0) ? p0 : (t4 == 1) ? p1 : (t4 == 2) ? p2 : p3;
    int src = ((lane & 7) << 2) | (lane >> 3);
    return __shfl_sync(0xffffffffu, expose, src);
}

// --------------------- approx eval: 1-term fp16 (256 mma) --------------------
// X*[c] = coords of warp-ray (lane>>2)+8c. Returns own-ray value (WITHOUT b3).
// Layer-1 recomputed per n-half via packed f32x2 FMA (no persistent A regs).
DINL float sdf_approx(const float* X0, const float* X1, const float* X2,
                      const float* __restrict__ w1d,
                      const float4* __restrict__ sBH,
                      const float4* __restrict__ bwv, int lane) {
    const int t4 = lane & 3;

    // pack X pairs once: PX[mt] holds (ray 2mt | ray 2mt+1)
    unsigned long long PX0[2], PX1[2], PX2[2];
#pragma unroll
    for (int mt = 0; mt < 2; ++mt) {
        PX0[mt] = pkf2(X0[2 * mt], X0[2 * mt + 1]);
        PX1[mt] = pkf2(X1[2 * mt], X1[2 * mt + 1]);
        PX2[mt] = pkf2(X2[2 * mt], X2[2 * mt + 1]);
    }

    float p0 = 0.f, p1 = 0.f, p2 = 0.f, p3 = 0.f;
#pragma unroll
    for (int half = 0; half < 2; ++half) {
        float C[2][8][4];
#pragma unroll
        for (int kc = 0; kc < 8; ++kc) {
            const int k0 = kc * 16 + 2 * t4;
            // duplicated W1 pairs for j = k0, k0+1, k0+8, k0+9
            ulonglong2 wA0 = *reinterpret_cast<const ulonglong2*>(w1d + k0 * 8);
            ulonglong2 wB0 = *reinterpret_cast<const ulonglong2*>(w1d + k0 * 8 + 4);
            ulonglong2 wA1 = *reinterpret_cast<const ulonglong2*>(w1d + (k0 + 1) * 8);
            ulonglong2 wB1 = *reinterpret_cast<const ulonglong2*>(w1d + (k0 + 1) * 8 + 4);
            ulonglong2 wA8 = *reinterpret_cast<const ulonglong2*>(w1d + (k0 + 8) * 8);
            ulonglong2 wB8 = *reinterpret_cast<const ulonglong2*>(w1d + (k0 + 8) * 8 + 4);
            ulonglong2 wA9 = *reinterpret_cast<const ulonglong2*>(w1d + (k0 + 9) * 8);
            ulonglong2 wB9 = *reinterpret_cast<const ulonglong2*>(w1d + (k0 + 9) * 8 + 4);

            uint32_t a[8];
#pragma unroll
            for (int mt = 0; mt < 2; ++mt) {
                unsigned long long h0 =
                    fma2_(wA0.x, PX0[mt], fma2_(wA0.y, PX1[mt],
                    fma2_(wB0.x, PX2[mt], wB0.y)));
                unsigned long long h1 =
                    fma2_(wA1.x, PX0[mt], fma2_(wA1.y, PX1[mt],
                    fma2_(wB1.x, PX2[mt], wB1.y)));
                unsigned long long h8 =
                    fma2_(wA8.x, PX0[mt], fma2_(wA8.y, PX1[mt],
                    fma2_(wB8.x, PX2[mt], wB8.y)));
                unsigned long long h9 =
                    fma2_(wA9.x, PX0[mt], fma2_(wA9.y, PX1[mt],
                    fma2_(wB9.x, PX2[mt], wB9.y)));
                float2 f0 = unpk(h0), f1 = unpk(h1), f8 = unpk(h8), f9 = unpk(h9);
                a[mt * 4 + 0] = pk16relu(f0.x, f1.x);
                a[mt * 4 + 1] = pk16relu(f0.y, f1.y);
                a[mt * 4 + 2] = pk16relu(f8.x, f9.x);
                a[mt * 4 + 3] = pk16relu(f8.y, f9.y);
            }

            const float4* bq = sBH + (kc * 8 + half * 4) * 32 + lane;
#pragma unroll
            for (int nbp = 0; nbp < 4; ++nbp) {
                float4 B = bq[nbp * 32];
                uint32_t b0 = __float_as_uint(B.x), b1 = __float_as_uint(B.y);
                uint32_t b2r = __float_as_uint(B.z), b3r = __float_as_uint(B.w);
                if (kc == 0) {
                    mma16_zero(C[0][2 * nbp],     a[0], a[1], a[2], a[3], b0, b1);
                    mma16_zero(C[1][2 * nbp],     a[4], a[5], a[6], a[7], b0, b1);
                    mma16_zero(C[0][2 * nbp + 1], a[0], a[1], a[2], a[3], b2r, b3r);
                    mma16_zero(C[1][2 * nbp + 1], a[4], a[5], a[6], a[7], b2r, b3r);
                } else {
                    mma16_acc(C[0][2 * nbp],     a[0], a[1], a[2], a[3], b0, b1);
                    mma16_acc(C[1][2 * nbp],     a[4], a[5], a[6], a[7], b0, b1);
                    mma16_acc(C[0][2 * nbp + 1], a[0], a[1], a[2], a[3], b2r, b3r);
                    mma16_acc(C[1][2 * nbp + 1], a[4], a[5], a[6], a[7], b2r, b3r);
                }
            }
        }
#pragma unroll
        for (int nb = 0; nb < 8; ++nb) {
            float4 bw = bwv[(half * 8 + nb) * 4 + t4];
            p0 = fmaf(fmaxf(C[0][nb][0] + bw.x, 0.f), bw.y, p0);
            p0 = fmaf(fmaxf(C[0][nb][1] + bw.z, 0.f), bw.w, p0);
            p1 = fmaf(fmaxf(C[0][nb][2] + bw.x, 0.f), bw.y, p1);
            p1 = fmaf(fmaxf(C[0][nb][3] + bw.z, 0.f), bw.w, p1);
            p2 = fmaf(fmaxf(C[1][nb][0] + bw.x, 0.f), bw.y, p2);
            p2 = fmaf(fmaxf(C[1][nb][1] + bw.z, 0.f), bw.w, p2);
            p3 = fmaf(fmaxf(C[1][nb][2] + bw.x, 0.f), bw.y, p3);
            p3 = fmaf(fmaxf(C[1][nb][3] + bw.z, 0.f), bw.w, p3);
        }
    }
    return expose_own(p0, p1, p2, p3, lane);
}

// --------------- precise eval: 3-term fp16 (768 mma, once per ray) -----------
// Quarter-split; scalar layer-1 per quarter; B_lo streamed from g_BL.
DINL float sdf_precise(const float* X0, const float* X1, const float* X2,
                       const float4* __restrict__ w1pack,
                       const float4* __restrict__ sBH,
                       const float4* __restrict__ bwv, int lane) {
    const int t4 = lane & 3;
    float p0 = 0.f, p1 = 0.f, p2 = 0.f, p3 = 0.f;
#pragma unroll 1
    for (int q = 0; q < 4; ++q) {
        float C[2][4][4];
#pragma unroll 1
        for (int kc = 0; kc < 8; ++kc) {
            const int k0 = kc * 16 + 2 * t4;
            float4 w0 = w1pack[k0];
            float4 w1 = w1pack[k0 + 1];
            float4 w8 = w1pack[k0 + 8];
            float4 w9 = w1pack[k0 + 9];
            uint32_t ahi[8], alo[8];
#pragma unroll
            for (int mt = 0; mt < 2; ++mt) {
                const int cA = 2 * mt, cB = 2 * mt + 1;
                float h[4][2], r[4][2];
                h[0][0] = fmaxf(fmaf(w0.x, X0[cA], fmaf(w0.y, X1[cA], fmaf(w0.z, X2[cA], w0.w))), 0.f);
                h[1][0] = fmaxf(fmaf(w1.x, X0[cA], fmaf(w1.y, X1[cA], fmaf(w1.z, X2[cA], w1.w))), 0.f);
                h[2][0] = fmaxf(fmaf(w8.x, X0[cA], fmaf(w8.y, X1[cA], fmaf(w8.z, X2[cA], w8.w))), 0.f);
                h[3][0] = fmaxf(fmaf(w9.x, X0[cA], fmaf(w9.y, X1[cA], fmaf(w9.z, X2[cA], w9.w))), 0.f);
                h[0][1] = fmaxf(fmaf(w0.x, X0[cB], fmaf(w0.y, X1[cB], fmaf(w0.z, X2[cB], w0.w))), 0.f);
                h[1][1] = fmaxf(fmaf(w1.x, X0[cB], fmaf(w1.y, X1[cB], fmaf(w1.z, X2[cB], w1.w))), 0.f);
                h[2][1] = fmaxf(fmaf(w8.x, X0[cB], fmaf(w8.y, X1[cB], fmaf(w8.z, X2[cB], w8.w))), 0.f);
                h[3][1] = fmaxf(fmaf(w9.x, X0[cB], fmaf(w9.y, X1[cB], fmaf(w9.z, X2[cB], w9.w))), 0.f);
#pragma unroll
                for (int s = 0; s < 4; ++s) {
                    r[s][0] = h[s][0] - f16_round(h[s][0]);
                    r[s][1] = h[s][1] - f16_round(h[s][1]);
                }
                ahi[mt * 4 + 0] = pk16(h[0][0], h[1][0]);
                ahi[mt * 4 + 1] = pk16(h[0][1], h[1][1]);
                ahi[mt * 4 + 2] = pk16(h[2][0], h[3][0]);
                ahi[mt * 4 + 3] = pk16(h[2][1], h[3][1]);
                alo[mt * 4 + 0] = pk16(r[0][0], r[1][0]);
                alo[mt * 4 + 1] = pk16(r[0][1], r[1][1]);
                alo[mt * 4 + 2] = pk16(r[2][0], r[3][0]);
                alo[mt * 4 + 3] = pk16(r[2][1], r[3][1]);
            }
            const float4* bqh = sBH + (kc * 8 + q * 2) * 32 + lane;
            const float4* bql = g_BL + (kc * 8 + q * 2) * 32 + lane;
#pragma unroll
            for (int p = 0; p < 2; ++p) {
                float4 BH = bqh[p * 32];
                float4 BL = bql[p * 32];
                uint32_t h0 = __float_as_uint(BH.x), h1 = __float_as_uint(BH.y);
                uint32_t h2 = __float_as_uint(BH.z), h3 = __float_as_uint(BH.w);
                uint32_t l0 = __float_as_uint(BL.x), l1 = __float_as_uint(BL.y);
                uint32_t l2 = __float_as_uint(BL.z), l3 = __float_as_uint(BL.w);
                if (kc == 0) {
                    mma16_zero(C[0][2 * p],     ahi[0], ahi[1], ahi[2], ahi[3], h0, h1);
                    mma16_zero(C[1][2 * p],     ahi[4], ahi[5], ahi[6], ahi[7], h0, h1);
                    mma16_zero(C[0][2 * p + 1], ahi[0], ahi[1], ahi[2], ahi[3], h2, h3);
                    mma16_zero(C[1][2 * p + 1], ahi[4], ahi[5], ahi[6], ahi[7], h2, h3);
                } else {
                    mma16_acc(C[0][2 * p],     ahi[0], ahi[1], ahi[2], ahi[3], h0, h1);
                    mma16_acc(C[1][2 * p],     ahi[4], ahi[5], ahi[6], ahi[7], h0, h1);
                    mma16_acc(C[0][2 * p + 1], ahi[0], ahi[1], ahi[2], ahi[3], h2, h3);
                    mma16_acc(C[1][2 * p + 1], ahi[4], ahi[5], ahi[6], ahi[7], h2, h3);
                }
                mma16_acc(C[0][2 * p],     alo[0], alo[1], alo[2], alo[3], h0, h1);
                mma16_acc(C[1][2 * p],     alo[4], alo[5], alo[6], alo[7], h0, h1);
                mma16_acc(C[0][2 * p + 1], alo[0], alo[1], alo[2], alo[3], h2, h3);
                mma16_acc(C[1][2 * p + 1], alo[4], alo[5], alo[6], alo[7], h2, h3);
                mma16_acc(C[0][2 * p],     ahi[0], ahi[1], ahi[2], ahi[3], l0, l1);
                mma16_acc(C[1][2 * p],     ahi[4], ahi[5], ahi[6], ahi[7], l0, l1);
                mma16_acc(C[0][2 * p + 1], ahi[0], ahi[1], ahi[2], ahi[3], l2, l3);
                mma16_acc(C[1][2 * p + 1], ahi[4], ahi[5], ahi[6], ahi[7], l2, l3);
            }
        }
#pragma unroll
        for (int j = 0; j < 4; ++j) {
            float4 bw = bwv[(q * 4 + j) * 4 + t4];
            p0 = fmaf(fmaxf(C[0][j][0] + bw.x, 0.f), bw.y, p0);
            p0 = fmaf(fmaxf(C[0][j][1] + bw.z, 0.f), bw.w, p0);
            p1 = fmaf(fmaxf(C[0][j][2] + bw.x, 0.f), bw.y, p1);
            p1 = fmaf(fmaxf(C[0][j][3] + bw.z, 0.f), bw.w, p1);
            p2 = fmaf(fmaxf(C[1][j][0] + bw.x, 0.f), bw.y, p2);
            p2 = fmaf(fmaxf(C[1][j][1] + bw.z, 0.f), bw.w, p2);
            p3 = fmaf(fmaxf(C[1][j][2] + bw.x, 0.f), bw.y, p3);
            p3 = fmaf(fmaxf(C[1][j][3] + bw.z, 0.f), bw.w, p3);
        }
    }
    return expose_own(p0, p1, p2, p3, lane);
}

DINL void bcast_X(float x0, float x1, float x2, int lane,
                  float* X0, float* X1, float* X2) {
#pragma unroll
    for (int c = 0; c < 4; ++c) {
        int src = (lane >> 2) + 8 * c;
        X0[c] = __shfl_sync(0xffffffffu, x0, src);
        X1[c] = __shfl_sync(0xffffffffu, x1, src);
        X2[c] = __shfl_sync(0xffffffffu, x2, src);
    }
}

// ------------------------- prep kernel (B_lo pack) ---------------------------
// entry idx: (kc*8 + nbp)*32 + l; t=l&3, g=l>>2, k0=16kc+2t, n0=16nbp+g, n1=n0+8
__global__ void sdf_prep_kernel(const float* __restrict__ W2) {
    int idx = blockIdx.x * blockDim.x + threadIdx.x;
    if (idx >= 2048) return;
    int l = idx & 31, nbp = (idx >> 5) & 7, kc = idx >> 8;
    int t = l & 3, g = l >> 2;
    int n0 = nbp * 16 + g, n1 = n0 + 8;
    int k0 = kc * 16 + 2 * t;
    float a00 = W2[k0 * HN + n0],       a01 = W2[(k0 + 1) * HN + n0];
    float a08 = W2[(k0 + 8) * HN + n0], a09 = W2[(k0 + 9) * HN + n0];
    float b00 = W2[k0 * HN + n1],       b01 = W2[(k0 + 1) * HN + n1];
    float b08 = W2[(k0 + 8) * HN + n1], b09 = W2[(k0 + 9) * HN + n1];
    float4 vl;
    vl.x = __uint_as_float(pk16(a00 - f16_round(a00), a01 - f16_round(a01)));
    vl.y = __uint_as_float(pk16(a08 - f16_round(a08), a09 - f16_round(a09)));
    vl.z = __uint_as_float(pk16(b00 - f16_round(b00), b01 - f16_round(b01)));
    vl.w = __uint_as_float(pk16(b08 - f16_round(b08), b09 - f16_round(b09)));
    g_BL[idx] = vl;
}

// ------------------------------- main kernel ---------------------------------
__global__ void __launch_bounds__(128, 4) sdf_mma_kernel(
    const float* __restrict__ rays,
    const float* __restrict__ W1, const float* __restrict__ b1,
    const float* __restrict__ W2, const float* __restrict__ b2,
    const float* __restrict__ W3, const float* __restrict__ b3,
    const float* __restrict__ R1, const float* __restrict__ rb1,
    const float* __restrict__ R2, const float* __restrict__ rb2,
    float* __restrict__ out, int n)
{
    extern __shared__ float smem[];
    const int tid = threadIdx.x;
    const int lane = tid & 31;

    // ---- stage B_hi = W2 fp16 in mma-fragment pack ----
    for (int idx = tid; idx < 2048; idx += 128) {
        int l = idx & 31, nbp = (idx >> 5) & 7, kc = idx >> 8;
        int t = l & 3, g = l >> 2;
        int n0 = nbp * 16 + g, n1 = n0 + 8;
        int k0 = kc * 16 + 2 * t;
        float4 vh;
        vh.x = __uint_as_float(pk16(W2[k0 * HN + n0],       W2[(k0 + 1) * HN + n0]));
        vh.y = __uint_as_float(pk16(W2[(k0 + 8) * HN + n0], W2[(k0 + 9) * HN + n0]));
        vh.z = __uint_as_float(pk16(W2[k0 * HN + n1],       W2[(k0 + 1) * HN + n1]));
        vh.w = __uint_as_float(pk16(W2[(k0 + 8) * HN + n1], W2[(k0 + 9) * HN + n1]));
        reinterpret_cast<float4*>(smem + OFF_BH)[idx] = vh;
    }
    // ---- stage duplicated W1 pairs + small weights ----
    {
        float4* w1v  = reinterpret_cast<float4*>(smem + OFF_W1);
        float2* bwv2 = reinterpret_cast<float2*>(smem + OFF_BW);
        float4* r1av = reinterpret_cast<float4*>(smem + OFF_R1A);
        float4* r1bv = reinterpret_cast<float4*>(smem + OFF_R1B);
        float4* r2v  = reinterpret_cast<float4*>(smem + OFF_R2);
        for (int j = tid; j < HN; j += 128) {
            float wx = W1[j], wy = W1[HN + j], wz = W1[2 * HN + j], bb = b1[j];
            w1v[j]  = make_float4(wx, wy, wz, bb);
            float* d = smem + OFF_W1D + j * 8;
            d[0] = wx; d[1] = wx; d[2] = wy; d[3] = wy;
            d[4] = wz; d[5] = wz; d[6] = bb; d[7] = bb;
            bwv2[j] = make_float2(b2[j], W3[j]);
            r1av[j] = make_float4(R1[j], R1[HN + j], R1[2 * HN + j], R1[3 * HN + j]);
            r1bv[j] = make_float4(R1[4 * HN + j], R1[5 * HN + j], rb1[j], 0.0f);
            r2v[j]  = make_float4(R2[3 * j], R2[3 * j + 1], R2[3 * j + 2], 0.0f);
        }
    }
    if (tid < 3) smem[OFF_MISC + tid] = rb2[tid];
    if (tid == 0) smem[OFF_MISC + 3] = b3[0];
    __syncthreads();

    const float4* w1pack = reinterpret_cast<const float4*>(smem + OFF_W1);
    const float*  w1d    = smem + OFF_W1D;
    const float4* sBH    = reinterpret_cast<const float4*>(smem + OFF_BH);
    const float4* bwv    = reinterpret_cast<const float4*>(smem + OFF_BW);
    const float bb3 = smem[OFF_MISC + 3];

    int ray = blockIdx.x * 128 + tid;
    const bool active = ray < n;
    if (!active) ray = n - 1;
    const float ro0 = rays[ray * 6 + 0], ro1 = rays[ray * 6 + 1], ro2 = rays[ray * 6 + 2];
    const float rd0 = rays[ray * 6 + 3], rd1 = rays[ray * 6 + 4], rd2 = rays[ray * 6 + 5];

    // ============ sphere tracing (warp-wide early break) ============
    float cd = kNEAR;
    bool hit = false;
#pragma unroll 1
    for (int it = 0; it < kITERS; ++it) {
        float x0 = __fadd_rn(ro0, __fmul_rn(rd0, cd));
        float x1 = __fadd_rn(ro1, __fmul_rn(rd1, cd));
        float x2 = __fadd_rn(ro2, __fmul_rn(rd2, cd));
        float X0[4], X1[4], X2[4];
        bcast_X(x0, x1, x2, lane, X0, X1, X2);
        float dist = sdf_approx(X0, X1, X2, w1d, sBH, bwv, lane) + bb3;
        bool h = (dist < kEPS) && (cd >= kNEAR) && (cd <= kFAR);
        hit = hit || h;
        if (!hit) cd += dist;
        if (__all_sync(0xffffffffu, hit)) break;
    }

    // ============ reflectance MLP (scalar, cheap) ============
    float p0 = __fadd_rn(ro0, __fmul_rn(rd0, cd));
    float p1 = __fadd_rn(ro1, __fmul_rn(rd1, cd));
    float p2 = __fadd_rn(ro2, __fmul_rn(rd2, cd));
    float rgb0 = smem[OFF_MISC + 0], rgb1 = smem[OFF_MISC + 1], rgb2 = smem[OFF_MISC + 2];
    {
        const float4* r1a = reinterpret_cast<const float4*>(smem + OFF_R1A);
        const float4* r1b = reinterpret_cast<const float4*>(smem + OFF_R1B);
        const float4* r2v = reinterpret_cast<const float4*>(smem + OFF_R2);
#pragma unroll 4
        for (int j = 0; j < HN; ++j) {
            float4 a = r1a[j];
            float4 b = r1b[j];
            float hv = fmaf(a.x, p0, fmaf(a.y, p1, fmaf(a.z, p2,
                       fmaf(a.w, rd0, fmaf(b.x, rd1, fmaf(b.y, rd2, b.z))))));
            hv = fmaxf(hv, 0.0f);
            float4 w = r2v[j];
            rgb0 = fmaf(hv, w.x, rgb0);
            rgb1 = fmaf(hv, w.y, rgb1);
            rgb2 = fmaf(hv, w.z, rgb2);
        }
    }
    if (!hit) { rgb0 = 0.0f; rgb1 = 0.0f; rgb2 = 0.0f; }

    // ============ tube-point scan (approx ranking) ============
    float m_ap = __int_as_float(0x7f800000);
    int   bi   = 0;
#pragma unroll 1
    for (int i = 0; i <= kTP; ++i) {
        float t = kSTEP * (float)i;
        float x0 = __fadd_rn(ro0, __fmul_rn(rd0, t));
        float x1 = __fadd_rn(ro1, __fmul_rn(rd1, t));
        float x2 = __fadd_rn(ro2, __fmul_rn(rd2, t));
        float X0[4], X1[4], X2[4];
        bcast_X(x0, x1, x2, lane, X0, X1, X2);
        float sd = sdf_approx(X0, X1, X2, w1d, sBH, bwv, lane);
        if (sd < m_ap) { m_ap = sd; bi = i; }
    }
    // precise re-eval at the per-ray argmin point (tput == curr_min identity)
    float m;
    {
        float tb = kSTEP * (float)bi;
        float x0 = __fadd_rn(ro0, __fmul_rn(rd0, tb));
        float x1 = __fadd_rn(ro1, __fmul_rn(rd1, tb));
        float x2 = __fadd_rn(ro2, __fmul_rn(rd2, tb));
        float X0[4], X1[4], X2[4];
        bcast_X(x0, x1, x2, lane, X0, X1, X2);
        m = sdf_precise(X0, X1, X2, w1pack, sBH, bwv, lane) + bb3;
    }

    if (active) {
        float4 o;
        o.x = rgb0; o.y = rgb1; o.z = rgb2; o.w = -kALPHA * m;
        reinterpret_cast<float4*>(out)[ray] = o;
    }
}

extern "C" void kernel_launch(void* const* d_in, const int* in_sizes, int n_in,
                              void* d_out, int out_size) {
    const float* rays = (const float*)d_in[0];
    const float* W1   = (const float*)d_in[1];
    const float* b1   = (const float*)d_in[2];
    const float* W2   = (const float*)d_in[3];
    const float* b2   = (const float*)d_in[4];
    const float* W3   = (const float*)d_in[5];
    const float* b3   = (const float*)d_in[6];
    const float* R1   = (const float*)d_in[7];
    const float* rb1  = (const float*)d_in[8];
    const float* R2   = (const float*)d_in[9];
    const float* rb2  = (const float*)d_in[10];
    float* out = (float*)d_out;

    const int n = in_sizes[0] / 6;

    sdf_prep_kernel<<<16, 128>>>(W2);

    cudaFuncSetAttribute(sdf_mma_kernel,
                         cudaFuncAttributeMaxDynamicSharedMemorySize, SMEM_BYTES);

    const int grid = (n + 127) / 128;
    sdf_mma_kernel<<<grid, 128, SMEM_BYTES>>>(
        rays, W1, b1, W2, b2, W3, b3, R1, rb1, R2, rb2, out, n);
}

// round 14
// speedup vs baseline: 1.3410x; 1.3410x over previous
#include <cuda_runtime.h>
#include <cuda_fp16.h>
#include <cstdint>

// ---------------------------------------------------------------------------
// Neural-SDF ray march + tube min + reflectance.
// Warp-cooperative: 32 rays/warp; each SDF eval = 32x128x128 GEMM via
// mma.sync.m16n8k16 f16.
//   * march + tube scan: 1-term fp16 (256 mma/eval)
//   * column-3: ONE precise fp16 3-term eval per ray at the approx argmin
//   * A-hi held in regs; layer-2 split into two n-halves (C 64 regs live)
//   * __launch_bounds__(128,3): 12 warps/SM to keep the tensor pipe fed
//   * march break vote: hit OR cd > FAR (exited rays stop blocking the warp)
// ---------------------------------------------------------------------------

#define DINL __device__ __forceinline__

namespace {
constexpr int   HN     = 128;
constexpr float kNEAR  = 0.2f;
constexpr float kFAR   = 2.0f;
constexpr float kALPHA = 100.0f;
constexpr float kEPS   = 0.005f;
constexpr int   kITERS = 32;
constexpr int   kTP    = 32;
constexpr float kSTEP  = 0.0634765625f;  // (2 + 0.5*(2/32))/32, exact fp32

// shared memory layout (float offsets)
constexpr int OFF_BH   = 0;        // 8192 floats: W2 fp16-hi, float4 = 2 n-blocks
constexpr int OFF_BL   = 8192;     // 8192 floats: W2 fp16-lo residual, same layout
constexpr int OFF_W1   = 16384;    // float4[128]: (W1[0][k],W1[1][k],W1[2][k],b1[k])
constexpr int OFF_BW   = 16896;    // float2[128]: (b2[n], W3[n])
constexpr int OFF_R1A  = 17152;    // float4[128]: R1 rows 0..3
constexpr int OFF_R1B  = 17664;    // float4[128]: (R1[4][j],R1[5][j],rb1[j],0)
constexpr int OFF_R2   = 18176;    // float4[128]: (R2[j][0..2],0)
constexpr int OFF_MISC = 18688;    // rb2[0..2], b3
constexpr int SMEM_FLOATS = 18692;
constexpr int SMEM_BYTES  = SMEM_FLOATS * 4;
}  // namespace

// ----------------------------- helpers --------------------------------------
DINL uint32_t pk16(float e0, float e1) {   // low = rn(e0), high = rn(e1)
    uint32_t d;
    asm("cvt.rn.f16x2.f32 %0, %1, %2;" : "=r"(d) : "f"(e1), "f"(e0));
    return d;
}
DINL uint32_t pk16relu(float e0, float e1) {  // rn then clamp at 0
    uint32_t d;
    asm("cvt.rn.relu.f16x2.f32 %0, %1, %2;" : "=r"(d) : "f"(e1), "f"(e0));
    return d;
}
DINL float f16_round(float x) { return __half2float(__float2half_rn(x)); }

// ----------------------------- mma wrappers ---------------------------------
DINL void mma16_acc(float c[4], uint32_t a0, uint32_t a1, uint32_t a2,
                    uint32_t a3, uint32_t b0, uint32_t b1) {
    asm volatile(
        "mma.sync.aligned.m16n8k16.row.col.f32.f16.f16.f32 "
        "{%0,%1,%2,%3},{%4,%5,%6,%7},{%8,%9},{%0,%1,%2,%3};"
        : "+f"(c[0]), "+f"(c[1]), "+f"(c[2]), "+f"(c[3])
        : "r"(a0), "r"(a1), "r"(a2), "r"(a3), "r"(b0), "r"(b1));
}
DINL void mma16_zero(float c[4], uint32_t a0, uint32_t a1, uint32_t a2,
                     uint32_t a3, uint32_t b0, uint32_t b1) {
    float z = 0.0f;
    asm volatile(
        "mma.sync.aligned.m16n8k16.row.col.f32.f16.f16.f32 "
        "{%0,%1,%2,%3},{%4,%5,%6,%7},{%8,%9},{%10,%10,%10,%10};"
        : "=f"(c[0]), "=f"(c[1]), "=f"(c[2]), "=f"(c[3])
        : "r"(a0), "r"(a1), "r"(a2), "r"(a3), "r"(b0), "r"(b1), "f"(z));
}

// --------------------------- epilogue reduce ---------------------------------
// lane 4g+c exposes ray g+8c; owner lane l fetches from 4*(l&7)+(l>>3)
DINL float expose_own(float p0, float p1, float p2, float p3, int lane) {
    p0 += __shfl_xor_sync(0xffffffffu, p0, 1);
    p0 += __shfl_xor_sync(0xffffffffu, p0, 2);
    p1 += __shfl_xor_sync(0xffffffffu, p1, 1);
    p1 += __shfl_xor_sync(0xffffffffu, p1, 2);
    p2 += __shfl_xor_sync(0xffffffffu, p2, 1);
    p2 += __shfl_xor_sync(0xffffffffu, p2, 2);
    p3 += __shfl_xor_sync(0xffffffffu, p3, 1);
    p3 += __shfl_xor_sync(0xffffffffu, p3, 2);
    const int t4 = lane & 3;
    float expose = (t4 == 0) ? p0 : (t4 == 1) ? p1 : (t4 == 2) ? p2 : p3;
    int src = ((lane & 7) << 2) | (lane >> 3);
    return __shfl_sync(0xffffffffu, expose, src);
}

// --------------------- approx eval: 1-term fp16 (256 mma) --------------------
// X*[c] = coords of warp-ray (lane>>2)+8c. Returns own-ray value (WITHOUT b3).
DINL float sdf_approx(const float* X0, const float* X1, const float* X2,
                      const float4* __restrict__ w1pack,
                      const float4* __restrict__ sBH,
                      const float4* __restrict__ bwv, int lane) {
    const int t4 = lane & 3;

    // ---- layer-1: pack A_hi for all kc (relu fused into cvt) ----
    uint32_t Ah[64];
#pragma unroll
    for (int kc = 0; kc < 8; ++kc) {
        const int k0 = kc * 16 + 2 * t4;
        float4 w0 = w1pack[k0];
        float4 w1 = w1pack[k0 + 1];
        float4 w8 = w1pack[k0 + 8];
        float4 w9 = w1pack[k0 + 9];
#pragma unroll
        for (int mt = 0; mt < 2; ++mt) {
            const int cA = 2 * mt, cB = 2 * mt + 1;
            float h0A = fmaf(w0.x, X0[cA], fmaf(w0.y, X1[cA], fmaf(w0.z, X2[cA], w0.w)));
            float h1A = fmaf(w1.x, X0[cA], fmaf(w1.y, X1[cA], fmaf(w1.z, X2[cA], w1.w)));
            float h8A = fmaf(w8.x, X0[cA], fmaf(w8.y, X1[cA], fmaf(w8.z, X2[cA], w8.w)));
            float h9A = fmaf(w9.x, X0[cA], fmaf(w9.y, X1[cA], fmaf(w9.z, X2[cA], w9.w)));
            float h0B = fmaf(w0.x, X0[cB], fmaf(w0.y, X1[cB], fmaf(w0.z, X2[cB], w0.w)));
            float h1B = fmaf(w1.x, X0[cB], fmaf(w1.y, X1[cB], fmaf(w1.z, X2[cB], w1.w)));
            float h8B = fmaf(w8.x, X0[cB], fmaf(w8.y, X1[cB], fmaf(w8.z, X2[cB], w8.w)));
            float h9B = fmaf(w9.x, X0[cB], fmaf(w9.y, X1[cB], fmaf(w9.z, X2[cB], w9.w)));
            Ah[kc * 8 + mt * 4 + 0] = pk16relu(h0A, h1A);
            Ah[kc * 8 + mt * 4 + 1] = pk16relu(h0B, h1B);
            Ah[kc * 8 + mt * 4 + 2] = pk16relu(h8A, h9A);
            Ah[kc * 8 + mt * 4 + 3] = pk16relu(h8B, h9B);
        }
    }

    // ---- layer-2 + epilogue in two n-halves (C = 64 regs live) ----
    float p0 = 0.f, p1 = 0.f, p2 = 0.f, p3 = 0.f;
#pragma unroll
    for (int half = 0; half < 2; ++half) {
        float C[2][8][4];
#pragma unroll
        for (int kc = 0; kc < 8; ++kc) {
            const uint32_t* a = Ah + kc * 8;
            const float4* bq = sBH + (kc * 8 + half * 4) * 32 + lane;
#pragma unroll
            for (int nbp = 0; nbp < 4; ++nbp) {
                float4 B = bq[nbp * 32];
                uint32_t b0 = __float_as_uint(B.x), b1 = __float_as_uint(B.y);
                uint32_t b2r = __float_as_uint(B.z), b3r = __float_as_uint(B.w);
                if (kc == 0) {
                    mma16_zero(C[0][2 * nbp],     a[0], a[1], a[2], a[3], b0, b1);
                    mma16_zero(C[1][2 * nbp],     a[4], a[5], a[6], a[7], b0, b1);
                    mma16_zero(C[0][2 * nbp + 1], a[0], a[1], a[2], a[3], b2r, b3r);
                    mma16_zero(C[1][2 * nbp + 1], a[4], a[5], a[6], a[7], b2r, b3r);
                } else {
                    mma16_acc(C[0][2 * nbp],     a[0], a[1], a[2], a[3], b0, b1);
                    mma16_acc(C[1][2 * nbp],     a[4], a[5], a[6], a[7], b0, b1);
                    mma16_acc(C[0][2 * nbp + 1], a[0], a[1], a[2], a[3], b2r, b3r);
                    mma16_acc(C[1][2 * nbp + 1], a[4], a[5], a[6], a[7], b2r, b3r);
                }
            }
        }
#pragma unroll
        for (int nb = 0; nb < 8; ++nb) {
            float4 bw = bwv[(half * 8 + nb) * 4 + t4];
            p0 = fmaf(fmaxf(C[0][nb][0] + bw.x, 0.f), bw.y, p0);
            p0 = fmaf(fmaxf(C[0][nb][1] + bw.z, 0.f), bw.w, p0);
            p1 = fmaf(fmaxf(C[0][nb][2] + bw.x, 0.f), bw.y, p1);
            p1 = fmaf(fmaxf(C[0][nb][3] + bw.z, 0.f), bw.w, p1);
            p2 = fmaf(fmaxf(C[1][nb][0] + bw.x, 0.f), bw.y, p2);
            p2 = fmaf(fmaxf(C[1][nb][1] + bw.z, 0.f), bw.w, p2);
            p3 = fmaf(fmaxf(C[1][nb][2] + bw.x, 0.f), bw.y, p3);
            p3 = fmaf(fmaxf(C[1][nb][3] + bw.z, 0.f), bw.w, p3);
        }
    }
    return expose_own(p0, p1, p2, p3, lane);
}

// --------------- precise eval: 3-term fp16 (768 mma, once per ray) -----------
DINL float sdf_precise(const float* X0, const float* X1, const float* X2,
                       const float4* __restrict__ w1pack,
                       const float4* __restrict__ sBH,
                       const float4* __restrict__ sBL,
                       const float4* __restrict__ bwv, int lane) {
    const int t4 = lane & 3;
    float p0 = 0.f, p1 = 0.f, p2 = 0.f, p3 = 0.f;
#pragma unroll 1
    for (int half = 0; half < 2; ++half) {
        float C[2][8][4];
#pragma unroll 1
        for (int kc = 0; kc < 8; ++kc) {
            // layer-1 recomputed per half (once per ray total: cheap)
            const int k0 = kc * 16 + 2 * t4;
            float4 w0 = w1pack[k0];
            float4 w1 = w1pack[k0 + 1];
            float4 w8 = w1pack[k0 + 8];
            float4 w9 = w1pack[k0 + 9];
            uint32_t ahi[8], alo[8];
#pragma unroll
            for (int mt = 0; mt < 2; ++mt) {
                const int cA = 2 * mt, cB = 2 * mt + 1;
                float h[4][2];
                h[0][0] = fmaxf(fmaf(w0.x, X0[cA], fmaf(w0.y, X1[cA], fmaf(w0.z, X2[cA], w0.w))), 0.f);
                h[1][0] = fmaxf(fmaf(w1.x, X0[cA], fmaf(w1.y, X1[cA], fmaf(w1.z, X2[cA], w1.w))), 0.f);
                h[2][0] = fmaxf(fmaf(w8.x, X0[cA], fmaf(w8.y, X1[cA], fmaf(w8.z, X2[cA], w8.w))), 0.f);
                h[3][0] = fmaxf(fmaf(w9.x, X0[cA], fmaf(w9.y, X1[cA], fmaf(w9.z, X2[cA], w9.w))), 0.f);
                h[0][1] = fmaxf(fmaf(w0.x, X0[cB], fmaf(w0.y, X1[cB], fmaf(w0.z, X2[cB], w0.w))), 0.f);
                h[1][1] = fmaxf(fmaf(w1.x, X0[cB], fmaf(w1.y, X1[cB], fmaf(w1.z, X2[cB], w1.w))), 0.f);
                h[2][1] = fmaxf(fmaf(w8.x, X0[cB], fmaf(w8.y, X1[cB], fmaf(w8.z, X2[cB], w8.w))), 0.f);
                h[3][1] = fmaxf(fmaf(w9.x, X0[cB], fmaf(w9.y, X1[cB], fmaf(w9.z, X2[cB], w9.w))), 0.f);
                float r[4][2];
#pragma unroll
                for (int s = 0; s < 4; ++s) {
                    r[s][0] = h[s][0] - f16_round(h[s][0]);
                    r[s][1] = h[s][1] - f16_round(h[s][1]);
                }
                ahi[mt * 4 + 0] = pk16(h[0][0], h[1][0]);
                ahi[mt * 4 + 1] = pk16(h[0][1], h[1][1]);
                ahi[mt * 4 + 2] = pk16(h[2][0], h[3][0]);
                ahi[mt * 4 + 3] = pk16(h[2][1], h[3][1]);
                alo[mt * 4 + 0] = pk16(r[0][0], r[1][0]);
                alo[mt * 4 + 1] = pk16(r[0][1], r[1][1]);
                alo[mt * 4 + 2] = pk16(r[2][0], r[3][0]);
                alo[mt * 4 + 3] = pk16(r[2][1], r[3][1]);
            }
            const float4* bqh = sBH + (kc * 8 + half * 4) * 32 + lane;
            const float4* bql = sBL + (kc * 8 + half * 4) * 32 + lane;
#pragma unroll
            for (int nbp = 0; nbp < 4; ++nbp) {
                float4 BH = bqh[nbp * 32];
                float4 BL = bql[nbp * 32];
                uint32_t h0 = __float_as_uint(BH.x), h1 = __float_as_uint(BH.y);
                uint32_t h2 = __float_as_uint(BH.z), h3 = __float_as_uint(BH.w);
                uint32_t l0 = __float_as_uint(BL.x), l1 = __float_as_uint(BL.y);
                uint32_t l2 = __float_as_uint(BL.z), l3 = __float_as_uint(BL.w);
                if (kc == 0) {
                    mma16_zero(C[0][2 * nbp],     ahi[0], ahi[1], ahi[2], ahi[3], h0, h1);
                    mma16_zero(C[1][2 * nbp],     ahi[4], ahi[5], ahi[6], ahi[7], h0, h1);
                    mma16_zero(C[0][2 * nbp + 1], ahi[0], ahi[1], ahi[2], ahi[3], h2, h3);
                    mma16_zero(C[1][2 * nbp + 1], ahi[4], ahi[5], ahi[6], ahi[7], h2, h3);
                } else {
                    mma16_acc(C[0][2 * nbp],     ahi[0], ahi[1], ahi[2], ahi[3], h0, h1);
                    mma16_acc(C[1][2 * nbp],     ahi[4], ahi[5], ahi[6], ahi[7], h0, h1);
                    mma16_acc(C[0][2 * nbp + 1], ahi[0], ahi[1], ahi[2], ahi[3], h2, h3);
                    mma16_acc(C[1][2 * nbp + 1], ahi[4], ahi[5], ahi[6], ahi[7], h2, h3);
                }
                mma16_acc(C[0][2 * nbp],     alo[0], alo[1], alo[2], alo[3], h0, h1);
                mma16_acc(C[1][2 * nbp],     alo[4], alo[5], alo[6], alo[7], h0, h1);
                mma16_acc(C[0][2 * nbp + 1], alo[0], alo[1], alo[2], alo[3], h2, h3);
                mma16_acc(C[1][2 * nbp + 1], alo[4], alo[5], alo[6], alo[7], h2, h3);
                mma16_acc(C[0][2 * nbp],     ahi[0], ahi[1], ahi[2], ahi[3], l0, l1);
                mma16_acc(C[1][2 * nbp],     ahi[4], ahi[5], ahi[6], ahi[7], l0, l1);
                mma16_acc(C[0][2 * nbp + 1], ahi[0], ahi[1], ahi[2], ahi[3], l2, l3);
                mma16_acc(C[1][2 * nbp + 1], ahi[4], ahi[5], ahi[6], ahi[7], l2, l3);
            }
        }
#pragma unroll
        for (int nb = 0; nb < 8; ++nb) {
            float4 bw = bwv[(half * 8 + nb) * 4 + t4];
            p0 = fmaf(fmaxf(C[0][nb][0] + bw.x, 0.f), bw.y, p0);
            p0 = fmaf(fmaxf(C[0][nb][1] + bw.z, 0.f), bw.w, p0);
            p1 = fmaf(fmaxf(C[0][nb][2] + bw.x, 0.f), bw.y, p1);
            p1 = fmaf(fmaxf(C[0][nb][3] + bw.z, 0.f), bw.w, p1);
            p2 = fmaf(fmaxf(C[1][nb][0] + bw.x, 0.f), bw.y, p2);
            p2 = fmaf(fmaxf(C[1][nb][1] + bw.z, 0.f), bw.w, p2);
            p3 = fmaf(fmaxf(C[1][nb][2] + bw.x, 0.f), bw.y, p3);
            p3 = fmaf(fmaxf(C[1][nb][3] + bw.z, 0.f), bw.w, p3);
        }
    }
    return expose_own(p0, p1, p2, p3, lane);
}

DINL void bcast_X(float x0, float x1, float x2, int lane,
                  float* X0, float* X1, float* X2) {
#pragma unroll
    for (int c = 0; c < 4; ++c) {
        int src = (lane >> 2) + 8 * c;
        X0[c] = __shfl_sync(0xffffffffu, x0, src);
        X1[c] = __shfl_sync(0xffffffffu, x1, src);
        X2[c] = __shfl_sync(0xffffffffu, x2, src);
    }
}

// ------------------------------- kernel -------------------------------------
__global__ void __launch_bounds__(128, 3) sdf_mma_kernel(
    const float* __restrict__ rays,
    const float* __restrict__ W1, const float* __restrict__ b1,
    const float* __restrict__ W2, const float* __restrict__ b2,
    const float* __restrict__ W3, const float* __restrict__ b3,
    const float* __restrict__ R1, const float* __restrict__ rb1,
    const float* __restrict__ R2, const float* __restrict__ rb2,
    float* __restrict__ out, int n)
{
    extern __shared__ float smem[];
    const int tid = threadIdx.x;
    const int lane = tid & 31;

    // ---- stage B = W2 fp16 hi/lo, float4 covering 2 n-blocks per entry ----
    for (int idx = tid; idx < 2048; idx += blockDim.x) {
        int l = idx & 31, nbp = (idx >> 5) & 7, kc = idx >> 8;
        int t = l & 3, g = l >> 2;
        int n0 = nbp * 16 + g, n1 = n0 + 8;
        int k0 = kc * 16 + 2 * t;
        float a00 = W2[k0 * HN + n0],      a01 = W2[(k0 + 1) * HN + n0];
        float a08 = W2[(k0 + 8) * HN + n0], a09 = W2[(k0 + 9) * HN + n0];
        float b00 = W2[k0 * HN + n1],      b01 = W2[(k0 + 1) * HN + n1];
        float b08 = W2[(k0 + 8) * HN + n1], b09 = W2[(k0 + 9) * HN + n1];
        float4 vh, vl;
        vh.x = __uint_as_float(pk16(a00, a01));
        vh.y = __uint_as_float(pk16(a08, a09));
        vh.z = __uint_as_float(pk16(b00, b01));
        vh.w = __uint_as_float(pk16(b08, b09));
        vl.x = __uint_as_float(pk16(a00 - f16_round(a00), a01 - f16_round(a01)));
        vl.y = __uint_as_float(pk16(a08 - f16_round(a08), a09 - f16_round(a09)));
        vl.z = __uint_as_float(pk16(b00 - f16_round(b00), b01 - f16_round(b01)));
        vl.w = __uint_as_float(pk16(b08 - f16_round(b08), b09 - f16_round(b09)));
        reinterpret_cast<float4*>(smem + OFF_BH)[idx] = vh;
        reinterpret_cast<float4*>(smem + OFF_BL)[idx] = vl;
    }
    // ---- small weights ----
    {
        float4* w1v  = reinterpret_cast<float4*>(smem + OFF_W1);
        float2* bwv2 = reinterpret_cast<float2*>(smem + OFF_BW);
        float4* r1av = reinterpret_cast<float4*>(smem + OFF_R1A);
        float4* r1bv = reinterpret_cast<float4*>(smem + OFF_R1B);
        float4* r2v  = reinterpret_cast<float4*>(smem + OFF_R2);
        for (int j = tid; j < HN; j += blockDim.x) {
            w1v[j]  = make_float4(W1[j], W1[HN + j], W1[2 * HN + j], b1[j]);
            bwv2[j] = make_float2(b2[j], W3[j]);
            r1av[j] = make_float4(R1[j], R1[HN + j], R1[2 * HN + j], R1[3 * HN + j]);
            r1bv[j] = make_float4(R1[4 * HN + j], R1[5 * HN + j], rb1[j], 0.0f);
            r2v[j]  = make_float4(R2[3 * j], R2[3 * j + 1], R2[3 * j + 2], 0.0f);
        }
    }
    if (tid < 3) smem[OFF_MISC + tid] = rb2[tid];
    if (tid == 0) smem[OFF_MISC + 3] = b3[0];
    __syncthreads();

    const float4* w1pack = reinterpret_cast<const float4*>(smem + OFF_W1);
    const float4* sBH    = reinterpret_cast<const float4*>(smem + OFF_BH);
    const float4* sBL    = reinterpret_cast<const float4*>(smem + OFF_BL);
    const float4* bwv    = reinterpret_cast<const float4*>(smem + OFF_BW);
    const float bb3 = smem[OFF_MISC + 3];

    int ray = blockIdx.x * blockDim.x + tid;
    const bool active = ray < n;
    if (!active) ray = n - 1;
    const float ro0 = rays[ray * 6 + 0], ro1 = rays[ray * 6 + 1], ro2 = rays[ray * 6 + 2];
    const float rd0 = rays[ray * 6 + 3], rd1 = rays[ray * 6 + 4], rd2 = rays[ray * 6 + 5];

    // ============ sphere tracing ============
    // Break vote counts a lane done when it hit OR marched past FAR (a ray
    // with cd > FAR can re-enter only via rare negative-dist steps; accepted).
    float cd = kNEAR;
    bool hit = false;
#pragma unroll 1
    for (int it = 0; it < kITERS; ++it) {
        float x0 = __fadd_rn(ro0, __fmul_rn(rd0, cd));
        float x1 = __fadd_rn(ro1, __fmul_rn(rd1, cd));
        float x2 = __fadd_rn(ro2, __fmul_rn(rd2, cd));
        float X0[4], X1[4], X2[4];
        bcast_X(x0, x1, x2, lane, X0, X1, X2);
        float dist = sdf_approx(X0, X1, X2, w1pack, sBH, bwv, lane) + bb3;
        bool h = (dist < kEPS) && (cd >= kNEAR) && (cd <= kFAR);
        hit = hit || h;
        if (!hit) cd += dist;
        if (__all_sync(0xffffffffu, hit || (cd > kFAR))) break;
    }

    // ============ reflectance MLP (scalar, cheap) ============
    float p0 = __fadd_rn(ro0, __fmul_rn(rd0, cd));
    float p1 = __fadd_rn(ro1, __fmul_rn(rd1, cd));
    float p2 = __fadd_rn(ro2, __fmul_rn(rd2, cd));
    float rgb0 = smem[OFF_MISC + 0], rgb1 = smem[OFF_MISC + 1], rgb2 = smem[OFF_MISC + 2];
    {
        const float4* r1a = reinterpret_cast<const float4*>(smem + OFF_R1A);
        const float4* r1b = reinterpret_cast<const float4*>(smem + OFF_R1B);
        const float4* r2v = reinterpret_cast<const float4*>(smem + OFF_R2);
#pragma unroll 4
        for (int j = 0; j < HN; ++j) {
            float4 a = r1a[j];
            float4 b = r1b[j];
            float hv = fmaf(a.x, p0, fmaf(a.y, p1, fmaf(a.z, p2,
                       fmaf(a.w, rd0, fmaf(b.x, rd1, fmaf(b.y, rd2, b.z))))));
            hv = fmaxf(hv, 0.0f);
            float4 w = r2v[j];
            rgb0 = fmaf(hv, w.x, rgb0);
            rgb1 = fmaf(hv, w.y, rgb1);
            rgb2 = fmaf(hv, w.z, rgb2);
        }
    }
    if (!hit) { rgb0 = 0.0f; rgb1 = 0.0f; rgb2 = 0.0f; }

    // ============ tube-point scan (approx ranking) ============
    float m_ap = __int_as_float(0x7f800000);
    int   bi   = 0;
#pragma unroll 1
    for (int i = 0; i <= kTP; ++i) {
        float t = kSTEP * (float)i;
        float x0 = __fadd_rn(ro0, __fmul_rn(rd0, t));
        float x1 = __fadd_rn(ro1, __fmul_rn(rd1, t));
        float x2 = __fadd_rn(ro2, __fmul_rn(rd2, t));
        float X0[4], X1[4], X2[4];
        bcast_X(x0, x1, x2, lane, X0, X1, X2);
        float sd = sdf_approx(X0, X1, X2, w1pack, sBH, bwv, lane);
        if (sd < m_ap) { m_ap = sd; bi = i; }
    }
    // precise re-eval at the per-ray argmin point (tput == curr_min identity)
    float m;
    {
        float tb = kSTEP * (float)bi;
        float x0 = __fadd_rn(ro0, __fmul_rn(rd0, tb));
        float x1 = __fadd_rn(ro1, __fmul_rn(rd1, tb));
        float x2 = __fadd_rn(ro2, __fmul_rn(rd2, tb));
        float X0[4], X1[4], X2[4];
        bcast_X(x0, x1, x2, lane, X0, X1, X2);
        m = sdf_precise(X0, X1, X2, w1pack, sBH, sBL, bwv, lane) + bb3;
    }

    if (active) {
        float4 o;
        o.x = rgb0; o.y = rgb1; o.z = rgb2; o.w = -kALPHA * m;
        reinterpret_cast<float4*>(out)[ray] = o;
    }
}

extern "C" void kernel_launch(void* const* d_in, const int* in_sizes, int n_in,
                              void* d_out, int out_size) {
    const float* rays = (const float*)d_in[0];
    const float* W1   = (const float*)d_in[1];
    const float* b1   = (const float*)d_in[2];
    const float* W2   = (const float*)d_in[3];
    const float* b2   = (const float*)d_in[4];
    const float* W3   = (const float*)d_in[5];
    const float* b3   = (const float*)d_in[6];
    const float* R1   = (const float*)d_in[7];
    const float* rb1  = (const float*)d_in[8];
    const float* R2   = (const float*)d_in[9];
    const float* rb2  = (const float*)d_in[10];
    float* out = (float*)d_out;

    const int n = in_sizes[0] / 6;

    cudaFuncSetAttribute(sdf_mma_kernel,
                         cudaFuncAttributeMaxDynamicSharedMemorySize, SMEM_BYTES);

    const int block = 128;
    const int grid = (n + block - 1) / block;
    sdf_mma_kernel<<<grid, block, SMEM_BYTES>>>(
        rays, W1, b1, W2, b2, W3, b3, R1, rb1, R2, rb2, out, n);
}

// round 15
// speedup vs baseline: 1.5190x; 1.1327x over previous
#include <cuda_runtime.h>
#include <cuda_fp16.h>
#include <cstdint>

// ---------------------------------------------------------------------------
// Neural-SDF ray march + tube min + reflectance.
// Warp-cooperative: 32 rays/warp; each SDF eval = 32x128x128 GEMM via
// mma.sync.m16n8k16 f16.
//   * layer-1 is ALSO a GEMM: one k16 pass with 2-term split in the k-slots
//     (xh*W1h + xh*W1l + xl*W1h + b1; error ~2^-22). Its C fragments map
//     1:1 onto layer-2's A fragments (lane-local relu+pack, no shuffles).
//   * march + tube scan: 1-term fp16 layer-2 (256 mma) + 32 layer-1 mma
//   * column-3: ONE precise fp16 3-term eval per ray at the approx argmin;
//     B_lo residuals streamed from a __device__ global (L2-resident)
//   * __launch_bounds__(128,3): 12 warps/SM
// ---------------------------------------------------------------------------

#define DINL __device__ __forceinline__

namespace {
constexpr int   HN     = 128;
constexpr float kNEAR  = 0.2f;
constexpr float kFAR   = 2.0f;
constexpr float kALPHA = 100.0f;
constexpr float kEPS   = 0.005f;
constexpr int   kITERS = 32;
constexpr int   kTP    = 32;
constexpr float kSTEP  = 0.0634765625f;  // (2 + 0.5*(2/32))/32, exact fp32

// shared memory layout (float offsets)
constexpr int OFF_BH   = 0;        // 8192: W2 fp16-hi frag pack (float4 = 2 nb)
constexpr int OFF_W1B  = 8192;     // 1024: layer-1 GEMM B fragments
constexpr int OFF_W1   = 9216;     // float4[128]: (W1[0][k],W1[1][k],W1[2][k],b1[k])
constexpr int OFF_BW   = 9728;     // float2[128]: (b2[n], W3[n])
constexpr int OFF_R1A  = 9984;     // float4[128]: R1 rows 0..3
constexpr int OFF_R1B  = 10496;    // float4[128]: (R1[4][j],R1[5][j],rb1[j],0)
constexpr int OFF_R2   = 11008;    // float4[128]: (R2[j][0..2],0)
constexpr int OFF_MISC = 11520;    // rb2[0..2], b3
constexpr int SMEM_FLOATS = 11524;
constexpr int SMEM_BYTES  = SMEM_FLOATS * 4;
}  // namespace

// W2 fp16 residuals in mma-fragment pack (precise eval only; L2-resident).
__device__ float4 g_BL[2048];

// ----------------------------- helpers --------------------------------------
DINL uint32_t pk16(float e0, float e1) {   // low = rn(e0), high = rn(e1)
    uint32_t d;
    asm("cvt.rn.f16x2.f32 %0, %1, %2;" : "=r"(d) : "f"(e1), "f"(e0));
    return d;
}
DINL uint32_t pk16relu(float e0, float e1) {
    uint32_t d;
    asm("cvt.rn.relu.f16x2.f32 %0, %1, %2;" : "=r"(d) : "f"(e1), "f"(e0));
    return d;
}
DINL float f16_round(float x) { return __half2float(__float2half_rn(x)); }
DINL float h2f_lo(uint32_t p) {
    float f;
    asm("{ .reg .b16 l, h; mov.b32 {l, h}, %1; cvt.f32.f16 %0, l; }"
        : "=f"(f) : "r"(p));
    return f;
}
DINL float h2f_hi(uint32_t p) {
    float f;
    asm("{ .reg .b16 l, h; mov.b32 {l, h}, %1; cvt.f32.f16 %0, h; }"
        : "=f"(f) : "r"(p));
    return f;
}

// ----------------------------- mma wrappers ---------------------------------
DINL void mma16_acc(float c[4], uint32_t a0, uint32_t a1, uint32_t a2,
                    uint32_t a3, uint32_t b0, uint32_t b1) {
    asm volatile(
        "mma.sync.aligned.m16n8k16.row.col.f32.f16.f16.f32 "
        "{%0,%1,%2,%3},{%4,%5,%6,%7},{%8,%9},{%0,%1,%2,%3};"
        : "+f"(c[0]), "+f"(c[1]), "+f"(c[2]), "+f"(c[3])
        : "r"(a0), "r"(a1), "r"(a2), "r"(a3), "r"(b0), "r"(b1));
}
DINL void mma16_zero(float c[4], uint32_t a0, uint32_t a1, uint32_t a2,
                     uint32_t a3, uint32_t b0, uint32_t b1) {
    float z = 0.0f;
    asm volatile(
        "mma.sync.aligned.m16n8k16.row.col.f32.f16.f16.f32 "
        "{%0,%1,%2,%3},{%4,%5,%6,%7},{%8,%9},{%10,%10,%10,%10};"
        : "=f"(c[0]), "=f"(c[1]), "=f"(c[2]), "=f"(c[3])
        : "r"(a0), "r"(a1), "r"(a2), "r"(a3), "r"(b0), "r"(b1), "f"(z));
}

// --------------------------- epilogue reduce ---------------------------------
// lane 4g+c exposes ray g+8c; owner lane l fetches from 4*(l&7)+(l>>3)
DINL float expose_own(float p0, float p1, float p2, float p3, int lane) {
    p0 += __shfl_xor_sync(0xffffffffu, p0, 1);
    p0 += __shfl_xor_sync(0xffffffffu, p0, 2);
    p1 += __shfl_xor_sync(0xffffffffu, p1, 1);
    p1 += __shfl_xor_sync(0xffffffffu, p1, 2);
    p2 += __shfl_xor_sync(0xffffffffu, p2, 1);
    p2 += __shfl_xor_sync(0xffffffffu, p2, 2);
    p3 += __shfl_xor_sync(0xffffffffu, p3, 1);
    p3 += __shfl_xor_sync(0xffffffffu, p3, 2);
    const int t4 = lane & 3;
    float expose = (t4 == 0) ? p0 : (t4 == 1) ? p1 : (t4 == 2) ? p2 : p3;
    int src = ((lane & 7) << 2) | (lane >> 3);
    return __shfl_sync(0xffffffffu, expose, src);
}

// x -> fp16 hi/lo packs for the layer-1 GEMM A operand
DINL void build_ray_pack(float X0, float X1, float X2,
                         uint32_t& hi01, uint32_t& hi2o,
                         uint32_t& lo01, uint32_t& lo2z) {
    hi01 = pk16(X0, X1);
    hi2o = pk16(X2, 1.0f);
    float l0 = X0 - h2f_lo(hi01);
    float l1 = X1 - h2f_hi(hi01);
    float l2 = X2 - h2f_lo(hi2o);
    lo01 = pk16(l0, l1);
    lo2z = pk16(l2, 0.0f);
}

// --------------------- approx eval: l1-GEMM + 1-term layer-2 -----------------
// (x0,x1,x2) = own ray coords. Returns own-ray value (WITHOUT b3).
DINL float sdf_approx(float x0, float x1, float x2,
                      const float4* __restrict__ w1b,
                      const float4* __restrict__ sBH,
                      const float4* __restrict__ bwv, int lane) {
    const int t4 = lane & 3;
    const int g  = lane >> 2;
    uint32_t Ah[64];

    // ---- layer-1 GEMM, one m-tile at a time (Cl1 is transient) ----
#pragma unroll
    for (int mt = 0; mt < 2; ++mt) {
        const int srcA = g + 16 * mt;   // row g   -> ray srcA
        const int srcB = srcA + 8;      // row g+8 -> ray srcB
        float xA0 = __shfl_sync(0xffffffffu, x0, srcA);
        float xA1 = __shfl_sync(0xffffffffu, x1, srcA);
        float xA2 = __shfl_sync(0xffffffffu, x2, srcA);
        float xB0 = __shfl_sync(0xffffffffu, x0, srcB);
        float xB1 = __shfl_sync(0xffffffffu, x1, srcB);
        float xB2 = __shfl_sync(0xffffffffu, x2, srcB);
        uint32_t hiA01, hiA2o, loA01, loA2z;
        uint32_t hiB01, hiB2o, loB01, loB2z;
        build_ray_pack(xA0, xA1, xA2, hiA01, hiA2o, loA01, loA2z);
        build_ray_pack(xB0, xB1, xB2, hiB01, hiB2o, loB01, loB2z);
        // A k-slots per t: a0/a1 = hi pairs (t even: (x0h,x1h); t odd: (x2h,1))
        //                  a2/a3 = lo pairs (t=0: (x0l,x1l); t=1: (x2l,0); else 0)
        uint32_t a0 = (t4 & 1) ? hiA2o : hiA01;
        uint32_t a1 = (t4 & 1) ? hiB2o : hiB01;
        uint32_t a2 = (t4 == 0) ? loA01 : (t4 == 1) ? loA2z : 0u;
        uint32_t a3 = (t4 == 0) ? loB01 : (t4 == 1) ? loB2z : 0u;

        float Cl1[16][4];
#pragma unroll
        for (int nbp = 0; nbp < 8; ++nbp) {
            float4 B = w1b[nbp * 32 + lane];
            mma16_zero(Cl1[2 * nbp],     a0, a1, a2, a3,
                       __float_as_uint(B.x), __float_as_uint(B.y));
            mma16_zero(Cl1[2 * nbp + 1], a0, a1, a2, a3,
                       __float_as_uint(B.z), __float_as_uint(B.w));
        }
        // Cl1 tile nb cols (2t,2t+1) == layer-2 A k-slots 8nb+2t,+1
#pragma unroll
        for (int kc = 0; kc < 8; ++kc) {
            Ah[kc * 8 + mt * 4 + 0] = pk16relu(Cl1[2 * kc][0],     Cl1[2 * kc][1]);
            Ah[kc * 8 + mt * 4 + 1] = pk16relu(Cl1[2 * kc][2],     Cl1[2 * kc][3]);
            Ah[kc * 8 + mt * 4 + 2] = pk16relu(Cl1[2 * kc + 1][0], Cl1[2 * kc + 1][1]);
            Ah[kc * 8 + mt * 4 + 3] = pk16relu(Cl1[2 * kc + 1][2], Cl1[2 * kc + 1][3]);
        }
    }

    // ---- layer-2 + epilogue in two n-halves (C = 64 regs live) ----
    float p0 = 0.f, p1 = 0.f, p2 = 0.f, p3 = 0.f;
#pragma unroll
    for (int half = 0; half < 2; ++half) {
        float C[2][8][4];
#pragma unroll
        for (int kc = 0; kc < 8; ++kc) {
            const uint32_t* a = Ah + kc * 8;
            const float4* bq = sBH + (kc * 8 + half * 4) * 32 + lane;
#pragma unroll
            for (int nbp = 0; nbp < 4; ++nbp) {
                float4 B = bq[nbp * 32];
                uint32_t b0 = __float_as_uint(B.x), b1 = __float_as_uint(B.y);
                uint32_t b2r = __float_as_uint(B.z), b3r = __float_as_uint(B.w);
                if (kc == 0) {
                    mma16_zero(C[0][2 * nbp],     a[0], a[1], a[2], a[3], b0, b1);
                    mma16_zero(C[1][2 * nbp],     a[4], a[5], a[6], a[7], b0, b1);
                    mma16_zero(C[0][2 * nbp + 1], a[0], a[1], a[2], a[3], b2r, b3r);
                    mma16_zero(C[1][2 * nbp + 1], a[4], a[5], a[6], a[7], b2r, b3r);
                } else {
                    mma16_acc(C[0][2 * nbp],     a[0], a[1], a[2], a[3], b0, b1);
                    mma16_acc(C[1][2 * nbp],     a[4], a[5], a[6], a[7], b0, b1);
                    mma16_acc(C[0][2 * nbp + 1], a[0], a[1], a[2], a[3], b2r, b3r);
                    mma16_acc(C[1][2 * nbp + 1], a[4], a[5], a[6], a[7], b2r, b3r);
                }
            }
        }
#pragma unroll
        for (int nb = 0; nb < 8; ++nb) {
            float4 bw = bwv[(half * 8 + nb) * 4 + t4];
            p0 = fmaf(fmaxf(C[0][nb][0] + bw.x, 0.f), bw.y, p0);
            p0 = fmaf(fmaxf(C[0][nb][1] + bw.z, 0.f), bw.w, p0);
            p1 = fmaf(fmaxf(C[0][nb][2] + bw.x, 0.f), bw.y, p1);
            p1 = fmaf(fmaxf(C[0][nb][3] + bw.z, 0.f), bw.w, p1);
            p2 = fmaf(fmaxf(C[1][nb][0] + bw.x, 0.f), bw.y, p2);
            p2 = fmaf(fmaxf(C[1][nb][1] + bw.z, 0.f), bw.w, p2);
            p3 = fmaf(fmaxf(C[1][nb][2] + bw.x, 0.f), bw.y, p3);
            p3 = fmaf(fmaxf(C[1][nb][3] + bw.z, 0.f), bw.w, p3);
        }
    }
    return expose_own(p0, p1, p2, p3, lane);
}

// --------------- precise eval: 3-term fp16 (768 mma, once per ray) -----------
// Scalar fp32 layer-1; B_lo streamed from g_BL (L2-resident).
// X*[c] = coords of warp-ray (lane>>2)+8c.
DINL float sdf_precise(const float* X0, const float* X1, const float* X2,
                       const float4* __restrict__ w1pack,
                       const float4* __restrict__ sBH,
                       const float4* __restrict__ bwv, int lane) {
    const int t4 = lane & 3;
    float p0 = 0.f, p1 = 0.f, p2 = 0.f, p3 = 0.f;
#pragma unroll 1
    for (int half = 0; half < 2; ++half) {
        float C[2][8][4];
#pragma unroll 1
        for (int kc = 0; kc < 8; ++kc) {
            const int k0 = kc * 16 + 2 * t4;
            float4 w0 = w1pack[k0];
            float4 w1 = w1pack[k0 + 1];
            float4 w8 = w1pack[k0 + 8];
            float4 w9 = w1pack[k0 + 9];
            uint32_t ahi[8], alo[8];
#pragma unroll
            for (int mt = 0; mt < 2; ++mt) {
                const int cA = 2 * mt, cB = 2 * mt + 1;
                float h[4][2];
                h[0][0] = fmaxf(fmaf(w0.x, X0[cA], fmaf(w0.y, X1[cA], fmaf(w0.z, X2[cA], w0.w))), 0.f);
                h[1][0] = fmaxf(fmaf(w1.x, X0[cA], fmaf(w1.y, X1[cA], fmaf(w1.z, X2[cA], w1.w))), 0.f);
                h[2][0] = fmaxf(fmaf(w8.x, X0[cA], fmaf(w8.y, X1[cA], fmaf(w8.z, X2[cA], w8.w))), 0.f);
                h[3][0] = fmaxf(fmaf(w9.x, X0[cA], fmaf(w9.y, X1[cA], fmaf(w9.z, X2[cA], w9.w))), 0.f);
                h[0][1] = fmaxf(fmaf(w0.x, X0[cB], fmaf(w0.y, X1[cB], fmaf(w0.z, X2[cB], w0.w))), 0.f);
                h[1][1] = fmaxf(fmaf(w1.x, X0[cB], fmaf(w1.y, X1[cB], fmaf(w1.z, X2[cB], w1.w))), 0.f);
                h[2][1] = fmaxf(fmaf(w8.x, X0[cB], fmaf(w8.y, X1[cB], fmaf(w8.z, X2[cB], w8.w))), 0.f);
                h[3][1] = fmaxf(fmaf(w9.x, X0[cB], fmaf(w9.y, X1[cB], fmaf(w9.z, X2[cB], w9.w))), 0.f);
                float r[4][2];
#pragma unroll
                for (int s = 0; s < 4; ++s) {
                    r[s][0] = h[s][0] - f16_round(h[s][0]);
                    r[s][1] = h[s][1] - f16_round(h[s][1]);
                }
                ahi[mt * 4 + 0] = pk16(h[0][0], h[1][0]);
                ahi[mt * 4 + 1] = pk16(h[0][1], h[1][1]);
                ahi[mt * 4 + 2] = pk16(h[2][0], h[3][0]);
                ahi[mt * 4 + 3] = pk16(h[2][1], h[3][1]);
                alo[mt * 4 + 0] = pk16(r[0][0], r[1][0]);
                alo[mt * 4 + 1] = pk16(r[0][1], r[1][1]);
                alo[mt * 4 + 2] = pk16(r[2][0], r[3][0]);
                alo[mt * 4 + 3] = pk16(r[2][1], r[3][1]);
            }
            const float4* bqh = sBH + (kc * 8 + half * 4) * 32 + lane;
            const float4* bql = g_BL + (kc * 8 + half * 4) * 32 + lane;
#pragma unroll
            for (int nbp = 0; nbp < 4; ++nbp) {
                float4 BH = bqh[nbp * 32];
                float4 BL = bql[nbp * 32];
                uint32_t h0 = __float_as_uint(BH.x), h1 = __float_as_uint(BH.y);
                uint32_t h2 = __float_as_uint(BH.z), h3 = __float_as_uint(BH.w);
                uint32_t l0 = __float_as_uint(BL.x), l1 = __float_as_uint(BL.y);
                uint32_t l2 = __float_as_uint(BL.z), l3 = __float_as_uint(BL.w);
                if (kc == 0) {
                    mma16_zero(C[0][2 * nbp],     ahi[0], ahi[1], ahi[2], ahi[3], h0, h1);
                    mma16_zero(C[1][2 * nbp],     ahi[4], ahi[5], ahi[6], ahi[7], h0, h1);
                    mma16_zero(C[0][2 * nbp + 1], ahi[0], ahi[1], ahi[2], ahi[3], h2, h3);
                    mma16_zero(C[1][2 * nbp + 1], ahi[4], ahi[5], ahi[6], ahi[7], h2, h3);
                } else {
                    mma16_acc(C[0][2 * nbp],     ahi[0], ahi[1], ahi[2], ahi[3], h0, h1);
                    mma16_acc(C[1][2 * nbp],     ahi[4], ahi[5], ahi[6], ahi[7], h0, h1);
                    mma16_acc(C[0][2 * nbp + 1], ahi[0], ahi[1], ahi[2], ahi[3], h2, h3);
                    mma16_acc(C[1][2 * nbp + 1], ahi[4], ahi[5], ahi[6], ahi[7], h2, h3);
                }
                mma16_acc(C[0][2 * nbp],     alo[0], alo[1], alo[2], alo[3], h0, h1);
                mma16_acc(C[1][2 * nbp],     alo[4], alo[5], alo[6], alo[7], h0, h1);
                mma16_acc(C[0][2 * nbp + 1], alo[0], alo[1], alo[2], alo[3], h2, h3);
                mma16_acc(C[1][2 * nbp + 1], alo[4], alo[5], alo[6], alo[7], h2, h3);
                mma16_acc(C[0][2 * nbp],     ahi[0], ahi[1], ahi[2], ahi[3], l0, l1);
                mma16_acc(C[1][2 * nbp],     ahi[4], ahi[5], ahi[6], ahi[7], l0, l1);
                mma16_acc(C[0][2 * nbp + 1], ahi[0], ahi[1], ahi[2], ahi[3], l2, l3);
                mma16_acc(C[1][2 * nbp + 1], ahi[4], ahi[5], ahi[6], ahi[7], l2, l3);
            }
        }
#pragma unroll
        for (int nb = 0; nb < 8; ++nb) {
            float4 bw = bwv[(half * 8 + nb) * 4 + t4];
            p0 = fmaf(fmaxf(C[0][nb][0] + bw.x, 0.f), bw.y, p0);
            p0 = fmaf(fmaxf(C[0][nb][1] + bw.z, 0.f), bw.w, p0);
            p1 = fmaf(fmaxf(C[0][nb][2] + bw.x, 0.f), bw.y, p1);
            p1 = fmaf(fmaxf(C[0][nb][3] + bw.z, 0.f), bw.w, p1);
            p2 = fmaf(fmaxf(C[1][nb][0] + bw.x, 0.f), bw.y, p2);
            p2 = fmaf(fmaxf(C[1][nb][1] + bw.z, 0.f), bw.w, p2);
            p3 = fmaf(fmaxf(C[1][nb][2] + bw.x, 0.f), bw.y, p3);
            p3 = fmaf(fmaxf(C[1][nb][3] + bw.z, 0.f), bw.w, p3);
        }
    }
    return expose_own(p0, p1, p2, p3, lane);
}

DINL void bcast_X(float x0, float x1, float x2, int lane,
                  float* X0, float* X1, float* X2) {
#pragma unroll
    for (int c = 0; c < 4; ++c) {
        int src = (lane >> 2) + 8 * c;
        X0[c] = __shfl_sync(0xffffffffu, x0, src);
        X1[c] = __shfl_sync(0xffffffffu, x1, src);
        X2[c] = __shfl_sync(0xffffffffu, x2, src);
    }
}

// ------------------------- prep kernel (B_lo pack) ---------------------------
__global__ void sdf_prep_kernel(const float* __restrict__ W2) {
    int idx = blockIdx.x * blockDim.x + threadIdx.x;
    if (idx >= 2048) return;
    int l = idx & 31, nbp = (idx >> 5) & 7, kc = idx >> 8;
    int t = l & 3, g = l >> 2;
    int n0 = nbp * 16 + g, n1 = n0 + 8;
    int k0 = kc * 16 + 2 * t;
    float a00 = W2[k0 * HN + n0],       a01 = W2[(k0 + 1) * HN + n0];
    float a08 = W2[(k0 + 8) * HN + n0], a09 = W2[(k0 + 9) * HN + n0];
    float b00 = W2[k0 * HN + n1],       b01 = W2[(k0 + 1) * HN + n1];
    float b08 = W2[(k0 + 8) * HN + n1], b09 = W2[(k0 + 9) * HN + n1];
    float4 vl;
    vl.x = __uint_as_float(pk16(a00 - f16_round(a00), a01 - f16_round(a01)));
    vl.y = __uint_as_float(pk16(a08 - f16_round(a08), a09 - f16_round(a09)));
    vl.z = __uint_as_float(pk16(b00 - f16_round(b00), b01 - f16_round(b01)));
    vl.w = __uint_as_float(pk16(b08 - f16_round(b08), b09 - f16_round(b09)));
    g_BL[idx] = vl;
}

// layer-1 GEMM B row content (k-slot s, column n):
//  s 0..2: W1h rows; s=3: b1h; s 4..6: W1 residual rows; s=7: b1 residual;
//  s 8..10: W1h rows (x_lo term); s >= 11: 0. (pk16 performs the fp16 rounding)
DINL float w1row(const float* __restrict__ W1, const float* __restrict__ b1,
                 int s, int n) {
    if (s < 3)  return W1[s * HN + n];
    if (s == 3) return b1[n];
    if (s < 7)  { float w = W1[(s - 4) * HN + n]; return w - f16_round(w); }
    if (s == 7) { float b = b1[n]; return b - f16_round(b); }
    if (s < 11) return W1[(s - 8) * HN + n];
    return 0.0f;
}

// ------------------------------- main kernel ---------------------------------
__global__ void __launch_bounds__(128, 3) sdf_mma_kernel(
    const float* __restrict__ rays,
    const float* __restrict__ W1, const float* __restrict__ b1,
    const float* __restrict__ W2, const float* __restrict__ b2,
    const float* __restrict__ W3, const float* __restrict__ b3,
    const float* __restrict__ R1, const float* __restrict__ rb1,
    const float* __restrict__ R2, const float* __restrict__ rb2,
    float* __restrict__ out, int n)
{
    extern __shared__ float smem[];
    const int tid = threadIdx.x;
    const int lane = tid & 31;

    // ---- stage B_hi = W2 fp16 in mma-fragment pack ----
    for (int idx = tid; idx < 2048; idx += 128) {
        int l = idx & 31, nbp = (idx >> 5) & 7, kc = idx >> 8;
        int t = l & 3, g = l >> 2;
        int n0 = nbp * 16 + g, n1 = n0 + 8;
        int k0 = kc * 16 + 2 * t;
        float4 vh;
        vh.x = __uint_as_float(pk16(W2[k0 * HN + n0],       W2[(k0 + 1) * HN + n0]));
        vh.y = __uint_as_float(pk16(W2[(k0 + 8) * HN + n0], W2[(k0 + 9) * HN + n0]));
        vh.z = __uint_as_float(pk16(W2[k0 * HN + n1],       W2[(k0 + 1) * HN + n1]));
        vh.w = __uint_as_float(pk16(W2[(k0 + 8) * HN + n1], W2[(k0 + 9) * HN + n1]));
        reinterpret_cast<float4*>(smem + OFF_BH)[idx] = vh;
    }
    // ---- stage W1B (layer-1 GEMM B fragments): entry (nbp)*32 + l ----
    //  b0 = rows (2t,2t+1) at n0=16nbp+g; b1 = rows (2t+8,2t+9); .z/.w same n1
    for (int idx = tid; idx < 256; idx += 128) {
        int l = idx & 31, nbp = idx >> 5;
        int t = l & 3, g = l >> 2;
        int n0 = nbp * 16 + g, n1 = n0 + 8;
        float4 v;
        v.x = __uint_as_float(pk16(w1row(W1, b1, 2 * t, n0),     w1row(W1, b1, 2 * t + 1, n0)));
        v.y = __uint_as_float(pk16(w1row(W1, b1, 2 * t + 8, n0), w1row(W1, b1, 2 * t + 9, n0)));
        v.z = __uint_as_float(pk16(w1row(W1, b1, 2 * t, n1),     w1row(W1, b1, 2 * t + 1, n1)));
        v.w = __uint_as_float(pk16(w1row(W1, b1, 2 * t + 8, n1), w1row(W1, b1, 2 * t + 9, n1)));
        reinterpret_cast<float4*>(smem + OFF_W1B)[idx] = v;
    }
    // ---- small weights ----
    {
        float4* w1v  = reinterpret_cast<float4*>(smem + OFF_W1);
        float2* bwv2 = reinterpret_cast<float2*>(smem + OFF_BW);
        float4* r1av = reinterpret_cast<float4*>(smem + OFF_R1A);
        float4* r1bv = reinterpret_cast<float4*>(smem + OFF_R1B);
        float4* r2v  = reinterpret_cast<float4*>(smem + OFF_R2);
        for (int j = tid; j < HN; j += 128) {
            w1v[j]  = make_float4(W1[j], W1[HN + j], W1[2 * HN + j], b1[j]);
            bwv2[j] = make_float2(b2[j], W3[j]);
            r1av[j] = make_float4(R1[j], R1[HN + j], R1[2 * HN + j], R1[3 * HN + j]);
            r1bv[j] = make_float4(R1[4 * HN + j], R1[5 * HN + j], rb1[j], 0.0f);
            r2v[j]  = make_float4(R2[3 * j], R2[3 * j + 1], R2[3 * j + 2], 0.0f);
        }
    }
    if (tid < 3) smem[OFF_MISC + tid] = rb2[tid];
    if (tid == 0) smem[OFF_MISC + 3] = b3[0];
    __syncthreads();

    const float4* w1pack = reinterpret_cast<const float4*>(smem + OFF_W1);
    const float4* w1b    = reinterpret_cast<const float4*>(smem + OFF_W1B);
    const float4* sBH    = reinterpret_cast<const float4*>(smem + OFF_BH);
    const float4* bwv    = reinterpret_cast<const float4*>(smem + OFF_BW);
    const float bb3 = smem[OFF_MISC + 3];

    int ray = blockIdx.x * 128 + tid;
    const bool active = ray < n;
    if (!active) ray = n - 1;
    const float ro0 = rays[ray * 6 + 0], ro1 = rays[ray * 6 + 1], ro2 = rays[ray * 6 + 2];
    const float rd0 = rays[ray * 6 + 3], rd1 = rays[ray * 6 + 4], rd2 = rays[ray * 6 + 5];

    // ============ sphere tracing (warp-wide early break) ============
    float cd = kNEAR;
    bool hit = false;
#pragma unroll 1
    for (int it = 0; it < kITERS; ++it) {
        float x0 = __fadd_rn(ro0, __fmul_rn(rd0, cd));
        float x1 = __fadd_rn(ro1, __fmul_rn(rd1, cd));
        float x2 = __fadd_rn(ro2, __fmul_rn(rd2, cd));
        float dist = sdf_approx(x0, x1, x2, w1b, sBH, bwv, lane) + bb3;
        bool h = (dist < kEPS) && (cd >= kNEAR) && (cd <= kFAR);
        hit = hit || h;
        if (!hit) cd += dist;
        if (__all_sync(0xffffffffu, hit)) break;
    }

    // ============ reflectance MLP (scalar, cheap) ============
    float p0 = __fadd_rn(ro0, __fmul_rn(rd0, cd));
    float p1 = __fadd_rn(ro1, __fmul_rn(rd1, cd));
    float p2 = __fadd_rn(ro2, __fmul_rn(rd2, cd));
    float rgb0 = smem[OFF_MISC + 0], rgb1 = smem[OFF_MISC + 1], rgb2 = smem[OFF_MISC + 2];
    {
        const float4* r1a = reinterpret_cast<const float4*>(smem + OFF_R1A);
        const float4* r1b = reinterpret_cast<const float4*>(smem + OFF_R1B);
        const float4* r2v = reinterpret_cast<const float4*>(smem + OFF_R2);
#pragma unroll 4
        for (int j = 0; j < HN; ++j) {
            float4 a = r1a[j];
            float4 b = r1b[j];
            float hv = fmaf(a.x, p0, fmaf(a.y, p1, fmaf(a.z, p2,
                       fmaf(a.w, rd0, fmaf(b.x, rd1, fmaf(b.y, rd2, b.z))))));
            hv = fmaxf(hv, 0.0f);
            float4 w = r2v[j];
            rgb0 = fmaf(hv, w.x, rgb0);
            rgb1 = fmaf(hv, w.y, rgb1);
            rgb2 = fmaf(hv, w.z, rgb2);
        }
    }
    if (!hit) { rgb0 = 0.0f; rgb1 = 0.0f; rgb2 = 0.0f; }

    // ============ tube-point scan (approx ranking) ============
    float m_ap = __int_as_float(0x7f800000);
    int   bi   = 0;
#pragma unroll 1
    for (int i = 0; i <= kTP; ++i) {
        float t = kSTEP * (float)i;
        float x0 = __fadd_rn(ro0, __fmul_rn(rd0, t));
        float x1 = __fadd_rn(ro1, __fmul_rn(rd1, t));
        float x2 = __fadd_rn(ro2, __fmul_rn(rd2, t));
        float sd = sdf_approx(x0, x1, x2, w1b, sBH, bwv, lane);
        if (sd < m_ap) { m_ap = sd; bi = i; }
    }
    // precise re-eval at the per-ray argmin point (tput == curr_min identity)
    float m;
    {
        float tb = kSTEP * (float)bi;
        float x0 = __fadd_rn(ro0, __fmul_rn(rd0, tb));
        float x1 = __fadd_rn(ro1, __fmul_rn(rd1, tb));
        float x2 = __fadd_rn(ro2, __fmul_rn(rd2, tb));
        float X0[4], X1[4], X2[4];
        bcast_X(x0, x1, x2, lane, X0, X1, X2);
        m = sdf_precise(X0, X1, X2, w1pack, sBH, bwv, lane) + bb3;
    }

    if (active) {
        float4 o;
        o.x = rgb0; o.y = rgb1; o.z = rgb2; o.w = -kALPHA * m;
        reinterpret_cast<float4*>(out)[ray] = o;
    }
}

extern "C" void kernel_launch(void* const* d_in, const int* in_sizes, int n_in,
                              void* d_out, int out_size) {
    const float* rays = (const float*)d_in[0];
    const float* W1   = (const float*)d_in[1];
    const float* b1   = (const float*)d_in[2];
    const float* W2   = (const float*)d_in[3];
    const float* b2   = (const float*)d_in[4];
    const float* W3   = (const float*)d_in[5];
    const float* b3   = (const float*)d_in[6];
    const float* R1   = (const float*)d_in[7];
    const float* rb1  = (const float*)d_in[8];
    const float* R2   = (const float*)d_in[9];
    const float* rb2  = (const float*)d_in[10];
    float* out = (float*)d_out;

    const int n = in_sizes[0] / 6;

    sdf_prep_kernel<<<16, 128>>>(W2);

    cudaFuncSetAttribute(sdf_mma_kernel,
                         cudaFuncAttributeMaxDynamicSharedMemorySize, SMEM_BYTES);

    const int grid = (n + 127) / 128;
    sdf_mma_kernel<<<grid, 128, SMEM_BYTES>>>(
        rays, W1, b1, W2, b2, W3, b3, R1, rb1, R2, rb2, out, n);
}

// round 16
// speedup vs baseline: 1.5429x; 1.0157x over previous
#include <cuda_runtime.h>
#include <cuda_fp16.h>
#include <cstdint>

// ---------------------------------------------------------------------------
// Neural-SDF ray march + tube min + reflectance.
// Warp-cooperative: 32 rays/warp; each SDF eval = 32x128x128 GEMM via
// mma.sync.m16n8k16 with fp16 accumulators in the approx path:
//   * layer-1 is a GEMM (2-term fp16 split in the k-slots, err ~2^-22);
//     its f16x2 C-fragments ARE layer-2's A-operand pairs (relu = max.f16x2)
//   * layer-2 accumulates in f16 (error ~2e-4 on the scan ranking)
//   * column-3: ONE precise f32-accumulate 3-term eval per ray at the approx
//     argmin; B_lo residuals streamed from a __device__ global (L2-resident)
//   * f16 C fragments halve register pressure -> __launch_bounds__(128,4)
// ---------------------------------------------------------------------------

#define DINL __device__ __forceinline__

namespace {
constexpr int   HN     = 128;
constexpr float kNEAR  = 0.2f;
constexpr float kFAR   = 2.0f;
constexpr float kALPHA = 100.0f;
constexpr float kEPS   = 0.005f;
constexpr int   kITERS = 32;
constexpr int   kTP    = 32;
constexpr float kSTEP  = 0.0634765625f;  // (2 + 0.5*(2/32))/32, exact fp32

// shared memory layout (float offsets)
constexpr int OFF_BH   = 0;        // 8192: W2 fp16-hi frag pack (float4 = 2 nb)
constexpr int OFF_W1B  = 8192;     // 1024: layer-1 GEMM B fragments
constexpr int OFF_W1   = 9216;     // float4[128]: (W1[0][k],W1[1][k],W1[2][k],b1[k])
constexpr int OFF_BW   = 9728;     // float2[128]: (b2[n], W3[n])  (precise epilogue)
constexpr int OFF_B2H  = 9984;     // 64 u32: b2 f16x2 pairs [(n,n+1) at nb*4+t]
constexpr int OFF_W3F  = 10048;    // 64 float2: W3 pairs, same indexing
constexpr int OFF_R1A  = 10176;    // float4[128]: R1 rows 0..3
constexpr int OFF_R1B  = 10688;    // float4[128]: (R1[4][j],R1[5][j],rb1[j],0)
constexpr int OFF_R2   = 11200;    // float4[128]: (R2[j][0..2],0)
constexpr int OFF_MISC = 11712;    // rb2[0..2], b3
constexpr int SMEM_FLOATS = 11716;
constexpr int SMEM_BYTES  = SMEM_FLOATS * 4;
}  // namespace

// W2 fp16 residuals in mma-fragment pack (precise eval only; L2-resident).
__device__ float4 g_BL[2048];

// ----------------------------- helpers --------------------------------------
DINL uint32_t pk16(float e0, float e1) {   // low = rn(e0), high = rn(e1)
    uint32_t d;
    asm("cvt.rn.f16x2.f32 %0, %1, %2;" : "=r"(d) : "f"(e1), "f"(e0));
    return d;
}
DINL float f16_round(float x) { return __half2float(__float2half_rn(x)); }
DINL float h2f_lo(uint32_t p) {
    float f;
    asm("{ .reg .b16 l, h; mov.b32 {l, h}, %1; cvt.f32.f16 %0, l; }"
        : "=f"(f) : "r"(p));
    return f;
}
DINL float h2f_hi(uint32_t p) {
    float f;
    asm("{ .reg .b16 l, h; mov.b32 {l, h}, %1; cvt.f32.f16 %0, h; }"
        : "=f"(f) : "r"(p));
    return f;
}
DINL uint32_t hadd2_(uint32_t a, uint32_t b) {
    uint32_t d;
    asm("add.f16x2 %0, %1, %2;" : "=r"(d) : "r"(a), "r"(b));
    return d;
}
DINL uint32_t hmax2z(uint32_t a) {   // relu on an f16x2 pair
    uint32_t d;
    asm("max.f16x2 %0, %1, %2;" : "=r"(d) : "r"(a), "r"(0u));
    return d;
}

// ----------------------------- mma wrappers ---------------------------------
// f32-accumulate (precise path)
DINL void mma16_acc(float c[4], uint32_t a0, uint32_t a1, uint32_t a2,
                    uint32_t a3, uint32_t b0, uint32_t b1) {
    asm volatile(
        "mma.sync.aligned.m16n8k16.row.col.f32.f16.f16.f32 "
        "{%0,%1,%2,%3},{%4,%5,%6,%7},{%8,%9},{%0,%1,%2,%3};"
        : "+f"(c[0]), "+f"(c[1]), "+f"(c[2]), "+f"(c[3])
        : "r"(a0), "r"(a1), "r"(a2), "r"(a3), "r"(b0), "r"(b1));
}
DINL void mma16_zero(float c[4], uint32_t a0, uint32_t a1, uint32_t a2,
                     uint32_t a3, uint32_t b0, uint32_t b1) {
    float z = 0.0f;
    asm volatile(
        "mma.sync.aligned.m16n8k16.row.col.f32.f16.f16.f32 "
        "{%0,%1,%2,%3},{%4,%5,%6,%7},{%8,%9},{%10,%10,%10,%10};"
        : "=f"(c[0]), "=f"(c[1]), "=f"(c[2]), "=f"(c[3])
        : "r"(a0), "r"(a1), "r"(a2), "r"(a3), "r"(b0), "r"(b1), "f"(z));
}
// f16-accumulate (approx path): C/D are 2 regs of f16x2
DINL void mmah_acc(uint32_t c[2], uint32_t a0, uint32_t a1, uint32_t a2,
                   uint32_t a3, uint32_t b0, uint32_t b1) {
    asm volatile(
        "mma.sync.aligned.m16n8k16.row.col.f16.f16.f16.f16 "
        "{%0,%1},{%2,%3,%4,%5},{%6,%7},{%0,%1};"
        : "+r"(c[0]), "+r"(c[1])
        : "r"(a0), "r"(a1), "r"(a2), "r"(a3), "r"(b0), "r"(b1));
}
DINL void mmah_zero(uint32_t c[2], uint32_t a0, uint32_t a1, uint32_t a2,
                    uint32_t a3, uint32_t b0, uint32_t b1) {
    asm volatile(
        "mma.sync.aligned.m16n8k16.row.col.f16.f16.f16.f16 "
        "{%0,%1},{%2,%3,%4,%5},{%6,%7},{%8,%8};"
        : "=r"(c[0]), "=r"(c[1])
        : "r"(a0), "r"(a1), "r"(a2), "r"(a3), "r"(b0), "r"(b1), "r"(0u));
}

// --------------------------- epilogue reduce ---------------------------------
// lane 4g+c exposes ray g+8c; owner lane l fetches from 4*(l&7)+(l>>3)
DINL float expose_own(float p0, float p1, float p2, float p3, int lane) {
    p0 += __shfl_xor_sync(0xffffffffu, p0, 1);
    p0 += __shfl_xor_sync(0xffffffffu, p0, 2);
    p1 += __shfl_xor_sync(0xffffffffu, p1, 1);
    p1 += __shfl_xor_sync(0xffffffffu, p1, 2);
    p2 += __shfl_xor_sync(0xffffffffu, p2, 1);
    p2 += __shfl_xor_sync(0xffffffffu, p2, 2);
    p3 += __shfl_xor_sync(0xffffffffu, p3, 1);
    p3 += __shfl_xor_sync(0xffffffffu, p3, 2);
    const int t4 = lane & 3;
    float expose = (t4 == 0) ? p0 : (t4 == 1) ? p1 : (t4 == 2) ? p2 : p3;
    int src = ((lane & 7) << 2) | (lane >> 3);
    return __shfl_sync(0xffffffffu, expose, src);
}

// x -> fp16 hi/lo packs for the layer-1 GEMM A operand
DINL void build_ray_pack(float X0, float X1, float X2,
                         uint32_t& hi01, uint32_t& hi2o,
                         uint32_t& lo01, uint32_t& lo2z) {
    hi01 = pk16(X0, X1);
    hi2o = pk16(X2, 1.0f);
    float l0 = X0 - h2f_lo(hi01);
    float l1 = X1 - h2f_hi(hi01);
    float l2 = X2 - h2f_lo(hi2o);
    lo01 = pk16(l0, l1);
    lo2z = pk16(l2, 0.0f);
}

// --------------------- approx eval: all-f16-accumulate -----------------------
// (x0,x1,x2) = own ray coords. Returns own-ray value (WITHOUT b3).
DINL float sdf_approx(float x0, float x1, float x2,
                      const float4* __restrict__ w1b,
                      const float4* __restrict__ sBH,
                      const uint32_t* __restrict__ b2h,
                      const float2* __restrict__ w3f, int lane) {
    const int t4 = lane & 3;
    const int g  = lane >> 2;
    uint32_t Ah[64];

    // ---- layer-1 GEMM, one m-tile at a time (f16 accumulate) ----
#pragma unroll
    for (int mt = 0; mt < 2; ++mt) {
        const int srcA = g + 16 * mt;
        const int srcB = srcA + 8;
        float xA0 = __shfl_sync(0xffffffffu, x0, srcA);
        float xA1 = __shfl_sync(0xffffffffu, x1, srcA);
        float xA2 = __shfl_sync(0xffffffffu, x2, srcA);
        float xB0 = __shfl_sync(0xffffffffu, x0, srcB);
        float xB1 = __shfl_sync(0xffffffffu, x1, srcB);
        float xB2 = __shfl_sync(0xffffffffu, x2, srcB);
        uint32_t hiA01, hiA2o, loA01, loA2z;
        uint32_t hiB01, hiB2o, loB01, loB2z;
        build_ray_pack(xA0, xA1, xA2, hiA01, hiA2o, loA01, loA2z);
        build_ray_pack(xB0, xB1, xB2, hiB01, hiB2o, loB01, loB2z);
        uint32_t a0 = (t4 & 1) ? hiA2o : hiA01;
        uint32_t a1 = (t4 & 1) ? hiB2o : hiB01;
        uint32_t a2 = (t4 == 0) ? loA01 : (t4 == 1) ? loA2z : 0u;
        uint32_t a3 = (t4 == 0) ? loB01 : (t4 == 1) ? loB2z : 0u;

        uint32_t Cl1[16][2];
#pragma unroll
        for (int nbp = 0; nbp < 8; ++nbp) {
            float4 B = w1b[nbp * 32 + lane];
            mmah_zero(Cl1[2 * nbp],     a0, a1, a2, a3,
                      __float_as_uint(B.x), __float_as_uint(B.y));
            mmah_zero(Cl1[2 * nbp + 1], a0, a1, a2, a3,
                      __float_as_uint(B.z), __float_as_uint(B.w));
        }
        // Cl1 tile nb pair-regs are EXACTLY layer-2 A pairs: relu and store.
#pragma unroll
        for (int kc = 0; kc < 8; ++kc) {
            Ah[kc * 8 + mt * 4 + 0] = hmax2z(Cl1[2 * kc][0]);
            Ah[kc * 8 + mt * 4 + 1] = hmax2z(Cl1[2 * kc][1]);
            Ah[kc * 8 + mt * 4 + 2] = hmax2z(Cl1[2 * kc + 1][0]);
            Ah[kc * 8 + mt * 4 + 3] = hmax2z(Cl1[2 * kc + 1][1]);
        }
    }

    // ---- layer-2 (f16 accumulate) + half2 epilogue, two n-halves ----
    float p0 = 0.f, p1 = 0.f, p2 = 0.f, p3 = 0.f;
#pragma unroll
    for (int half = 0; half < 2; ++half) {
        uint32_t C[2][8][2];
#pragma unroll
        for (int kc = 0; kc < 8; ++kc) {
            const uint32_t* a = Ah + kc * 8;
            const float4* bq = sBH + (kc * 8 + half * 4) * 32 + lane;
#pragma unroll
            for (int nbp = 0; nbp < 4; ++nbp) {
                float4 B = bq[nbp * 32];
                uint32_t b0 = __float_as_uint(B.x), b1 = __float_as_uint(B.y);
                uint32_t b2r = __float_as_uint(B.z), b3r = __float_as_uint(B.w);
                if (kc == 0) {
                    mmah_zero(C[0][2 * nbp],     a[0], a[1], a[2], a[3], b0, b1);
                    mmah_zero(C[1][2 * nbp],     a[4], a[5], a[6], a[7], b0, b1);
                    mmah_zero(C[0][2 * nbp + 1], a[0], a[1], a[2], a[3], b2r, b3r);
                    mmah_zero(C[1][2 * nbp + 1], a[4], a[5], a[6], a[7], b2r, b3r);
                } else {
                    mmah_acc(C[0][2 * nbp],     a[0], a[1], a[2], a[3], b0, b1);
                    mmah_acc(C[1][2 * nbp],     a[4], a[5], a[6], a[7], b0, b1);
                    mmah_acc(C[0][2 * nbp + 1], a[0], a[1], a[2], a[3], b2r, b3r);
                    mmah_acc(C[1][2 * nbp + 1], a[4], a[5], a[6], a[7], b2r, b3r);
                }
            }
        }
#pragma unroll
        for (int nb = 0; nb < 8; ++nb) {
            int gi = (half * 8 + nb) * 4 + t4;
            uint32_t bp = b2h[gi];
            float2 w3 = w3f[gi];
            uint32_t v;
            v = hmax2z(hadd2_(C[0][nb][0], bp));
            p0 = fmaf(h2f_lo(v), w3.x, fmaf(h2f_hi(v), w3.y, p0));
            v = hmax2z(hadd2_(C[0][nb][1], bp));
            p1 = fmaf(h2f_lo(v), w3.x, fmaf(h2f_hi(v), w3.y, p1));
            v = hmax2z(hadd2_(C[1][nb][0], bp));
            p2 = fmaf(h2f_lo(v), w3.x, fmaf(h2f_hi(v), w3.y, p2));
            v = hmax2z(hadd2_(C[1][nb][1], bp));
            p3 = fmaf(h2f_lo(v), w3.x, fmaf(h2f_hi(v), w3.y, p3));
        }
    }
    return expose_own(p0, p1, p2, p3, lane);
}

// --------------- precise eval: 3-term fp16, f32 accumulate -------------------
// Scalar fp32 layer-1; B_lo streamed from g_BL (L2-resident).
// X*[c] = coords of warp-ray (lane>>2)+8c.
DINL float sdf_precise(const float* X0, const float* X1, const float* X2,
                       const float4* __restrict__ w1pack,
                       const float4* __restrict__ sBH,
                       const float4* __restrict__ bwv, int lane) {
    const int t4 = lane & 3;
    float p0 = 0.f, p1 = 0.f, p2 = 0.f, p3 = 0.f;
#pragma unroll 1
    for (int half = 0; half < 2; ++half) {
        float C[2][8][4];
#pragma unroll 1
        for (int kc = 0; kc < 8; ++kc) {
            const int k0 = kc * 16 + 2 * t4;
            float4 w0 = w1pack[k0];
            float4 w1 = w1pack[k0 + 1];
            float4 w8 = w1pack[k0 + 8];
            float4 w9 = w1pack[k0 + 9];
            uint32_t ahi[8], alo[8];
#pragma unroll
            for (int mt = 0; mt < 2; ++mt) {
                const int cA = 2 * mt, cB = 2 * mt + 1;
                float h[4][2];
                h[0][0] = fmaxf(fmaf(w0.x, X0[cA], fmaf(w0.y, X1[cA], fmaf(w0.z, X2[cA], w0.w))), 0.f);
                h[1][0] = fmaxf(fmaf(w1.x, X0[cA], fmaf(w1.y, X1[cA], fmaf(w1.z, X2[cA], w1.w))), 0.f);
                h[2][0] = fmaxf(fmaf(w8.x, X0[cA], fmaf(w8.y, X1[cA], fmaf(w8.z, X2[cA], w8.w))), 0.f);
                h[3][0] = fmaxf(fmaf(w9.x, X0[cA], fmaf(w9.y, X1[cA], fmaf(w9.z, X2[cA], w9.w))), 0.f);
                h[0][1] = fmaxf(fmaf(w0.x, X0[cB], fmaf(w0.y, X1[cB], fmaf(w0.z, X2[cB], w0.w))), 0.f);
                h[1][1] = fmaxf(fmaf(w1.x, X0[cB], fmaf(w1.y, X1[cB], fmaf(w1.z, X2[cB], w1.w))), 0.f);
                h[2][1] = fmaxf(fmaf(w8.x, X0[cB], fmaf(w8.y, X1[cB], fmaf(w8.z, X2[cB], w8.w))), 0.f);
                h[3][1] = fmaxf(fmaf(w9.x, X0[cB], fmaf(w9.y, X1[cB], fmaf(w9.z, X2[cB], w9.w))), 0.f);
                float r[4][2];
#pragma unroll
                for (int s = 0; s < 4; ++s) {
                    r[s][0] = h[s][0] - f16_round(h[s][0]);
                    r[s][1] = h[s][1] - f16_round(h[s][1]);
                }
                ahi[mt * 4 + 0] = pk16(h[0][0], h[1][0]);
                ahi[mt * 4 + 1] = pk16(h[0][1], h[1][1]);
                ahi[mt * 4 + 2] = pk16(h[2][0], h[3][0]);
                ahi[mt * 4 + 3] = pk16(h[2][1], h[3][1]);
                alo[mt * 4 + 0] = pk16(r[0][0], r[1][0]);
                alo[mt * 4 + 1] = pk16(r[0][1], r[1][1]);
                alo[mt * 4 + 2] = pk16(r[2][0], r[3][0]);
                alo[mt * 4 + 3] = pk16(r[2][1], r[3][1]);
            }
            const float4* bqh = sBH + (kc * 8 + half * 4) * 32 + lane;
            const float4* bql = g_BL + (kc * 8 + half * 4) * 32 + lane;
#pragma unroll
            for (int nbp = 0; nbp < 4; ++nbp) {
                float4 BH = bqh[nbp * 32];
                float4 BL = bql[nbp * 32];
                uint32_t h0 = __float_as_uint(BH.x), h1 = __float_as_uint(BH.y);
                uint32_t h2 = __float_as_uint(BH.z), h3 = __float_as_uint(BH.w);
                uint32_t l0 = __float_as_uint(BL.x), l1 = __float_as_uint(BL.y);
                uint32_t l2 = __float_as_uint(BL.z), l3 = __float_as_uint(BL.w);
                if (kc == 0) {
                    mma16_zero(C[0][2 * nbp],     ahi[0], ahi[1], ahi[2], ahi[3], h0, h1);
                    mma16_zero(C[1][2 * nbp],     ahi[4], ahi[5], ahi[6], ahi[7], h0, h1);
                    mma16_zero(C[0][2 * nbp + 1], ahi[0], ahi[1], ahi[2], ahi[3], h2, h3);
                    mma16_zero(C[1][2 * nbp + 1], ahi[4], ahi[5], ahi[6], ahi[7], h2, h3);
                } else {
                    mma16_acc(C[0][2 * nbp],     ahi[0], ahi[1], ahi[2], ahi[3], h0, h1);
                    mma16_acc(C[1][2 * nbp],     ahi[4], ahi[5], ahi[6], ahi[7], h0, h1);
                    mma16_acc(C[0][2 * nbp + 1], ahi[0], ahi[1], ahi[2], ahi[3], h2, h3);
                    mma16_acc(C[1][2 * nbp + 1], ahi[4], ahi[5], ahi[6], ahi[7], h2, h3);
                }
                mma16_acc(C[0][2 * nbp],     alo[0], alo[1], alo[2], alo[3], h0, h1);
                mma16_acc(C[1][2 * nbp],     alo[4], alo[5], alo[6], alo[7], h0, h1);
                mma16_acc(C[0][2 * nbp + 1], alo[0], alo[1], alo[2], alo[3], h2, h3);
                mma16_acc(C[1][2 * nbp + 1], alo[4], alo[5], alo[6], alo[7], h2, h3);
                mma16_acc(C[0][2 * nbp],     ahi[0], ahi[1], ahi[2], ahi[3], l0, l1);
                mma16_acc(C[1][2 * nbp],     ahi[4], ahi[5], ahi[6], ahi[7], l0, l1);
                mma16_acc(C[0][2 * nbp + 1], ahi[0], ahi[1], ahi[2], ahi[3], l2, l3);
                mma16_acc(C[1][2 * nbp + 1], ahi[4], ahi[5], ahi[6], ahi[7], l2, l3);
            }
        }
#pragma unroll
        for (int nb = 0; nb < 8; ++nb) {
            float4 bw = bwv[(half * 8 + nb) * 4 + t4];
            p0 = fmaf(fmaxf(C[0][nb][0] + bw.x, 0.f), bw.y, p0);
            p0 = fmaf(fmaxf(C[0][nb][1] + bw.z, 0.f), bw.w, p0);
            p1 = fmaf(fmaxf(C[0][nb][2] + bw.x, 0.f), bw.y, p1);
            p1 = fmaf(fmaxf(C[0][nb][3] + bw.z, 0.f), bw.w, p1);
            p2 = fmaf(fmaxf(C[1][nb][0] + bw.x, 0.f), bw.y, p2);
            p2 = fmaf(fmaxf(C[1][nb][1] + bw.z, 0.f), bw.w, p2);
            p3 = fmaf(fmaxf(C[1][nb][2] + bw.x, 0.f), bw.y, p3);
            p3 = fmaf(fmaxf(C[1][nb][3] + bw.z, 0.f), bw.w, p3);
        }
    }
    return expose_own(p0, p1, p2, p3, lane);
}

DINL void bcast_X(float x0, float x1, float x2, int lane,
                  float* X0, float* X1, float* X2) {
#pragma unroll
    for (int c = 0; c < 4; ++c) {
        int src = (lane >> 2) + 8 * c;
        X0[c] = __shfl_sync(0xffffffffu, x0, src);
        X1[c] = __shfl_sync(0xffffffffu, x1, src);
        X2[c] = __shfl_sync(0xffffffffu, x2, src);
    }
}

// ------------------------- prep kernel (B_lo pack) ---------------------------
__global__ void sdf_prep_kernel(const float* __restrict__ W2) {
    int idx = blockIdx.x * blockDim.x + threadIdx.x;
    if (idx >= 2048) return;
    int l = idx & 31, nbp = (idx >> 5) & 7, kc = idx >> 8;
    int t = l & 3, g = l >> 2;
    int n0 = nbp * 16 + g, n1 = n0 + 8;
    int k0 = kc * 16 + 2 * t;
    float a00 = W2[k0 * HN + n0],       a01 = W2[(k0 + 1) * HN + n0];
    float a08 = W2[(k0 + 8) * HN + n0], a09 = W2[(k0 + 9) * HN + n0];
    float b00 = W2[k0 * HN + n1],       b01 = W2[(k0 + 1) * HN + n1];
    float b08 = W2[(k0 + 8) * HN + n1], b09 = W2[(k0 + 9) * HN + n1];
    float4 vl;
    vl.x = __uint_as_float(pk16(a00 - f16_round(a00), a01 - f16_round(a01)));
    vl.y = __uint_as_float(pk16(a08 - f16_round(a08), a09 - f16_round(a09)));
    vl.z = __uint_as_float(pk16(b00 - f16_round(b00), b01 - f16_round(b01)));
    vl.w = __uint_as_float(pk16(b08 - f16_round(b08), b09 - f16_round(b09)));
    g_BL[idx] = vl;
}

// layer-1 GEMM B row content (k-slot s, column n):
//  s 0..2: W1h rows; s=3: b1h; s 4..6: W1 residual rows; s=7: b1 residual;
//  s 8..10: W1h rows (x_lo term); s >= 11: 0. (pk16 performs the fp16 rounding)
DINL float w1row(const float* __restrict__ W1, const float* __restrict__ b1,
                 int s, int n) {
    if (s < 3)  return W1[s * HN + n];
    if (s == 3) return b1[n];
    if (s < 7)  { float w = W1[(s - 4) * HN + n]; return w - f16_round(w); }
    if (s == 7) { float b = b1[n]; return b - f16_round(b); }
    if (s < 11) return W1[(s - 8) * HN + n];
    return 0.0f;
}

// ------------------------------- main kernel ---------------------------------
__global__ void __launch_bounds__(128, 4) sdf_mma_kernel(
    const float* __restrict__ rays,
    const float* __restrict__ W1, const float* __restrict__ b1,
    const float* __restrict__ W2, const float* __restrict__ b2,
    const float* __restrict__ W3, const float* __restrict__ b3,
    const float* __restrict__ R1, const float* __restrict__ rb1,
    const float* __restrict__ R2, const float* __restrict__ rb2,
    float* __restrict__ out, int n)
{
    extern __shared__ float smem[];
    const int tid = threadIdx.x;
    const int lane = tid & 31;

    // ---- stage B_hi = W2 fp16 in mma-fragment pack ----
    for (int idx = tid; idx < 2048; idx += 128) {
        int l = idx & 31, nbp = (idx >> 5) & 7, kc = idx >> 8;
        int t = l & 3, g = l >> 2;
        int n0 = nbp * 16 + g, n1 = n0 + 8;
        int k0 = kc * 16 + 2 * t;
        float4 vh;
        vh.x = __uint_as_float(pk16(W2[k0 * HN + n0],       W2[(k0 + 1) * HN + n0]));
        vh.y = __uint_as_float(pk16(W2[(k0 + 8) * HN + n0], W2[(k0 + 9) * HN + n0]));
        vh.z = __uint_as_float(pk16(W2[k0 * HN + n1],       W2[(k0 + 1) * HN + n1]));
        vh.w = __uint_as_float(pk16(W2[(k0 + 8) * HN + n1], W2[(k0 + 9) * HN + n1]));
        reinterpret_cast<float4*>(smem + OFF_BH)[idx] = vh;
    }
    // ---- stage W1B (layer-1 GEMM B fragments) ----
    for (int idx = tid; idx < 256; idx += 128) {
        int l = idx & 31, nbp = idx >> 5;
        int t = l & 3, g = l >> 2;
        int n0 = nbp * 16 + g, n1 = n0 + 8;
        float4 v;
        v.x = __uint_as_float(pk16(w1row(W1, b1, 2 * t, n0),     w1row(W1, b1, 2 * t + 1, n0)));
        v.y = __uint_as_float(pk16(w1row(W1, b1, 2 * t + 8, n0), w1row(W1, b1, 2 * t + 9, n0)));
        v.z = __uint_as_float(pk16(w1row(W1, b1, 2 * t, n1),     w1row(W1, b1, 2 * t + 1, n1)));
        v.w = __uint_as_float(pk16(w1row(W1, b1, 2 * t + 8, n1), w1row(W1, b1, 2 * t + 9, n1)));
        reinterpret_cast<float4*>(smem + OFF_W1B)[idx] = v;
    }
    // ---- epilogue tables: b2 f16x2 pairs + W3 float2 pairs ----
    for (int idx = tid; idx < 64; idx += 128) {
        int nb = idx >> 2, t = idx & 3;
        int n0 = nb * 8 + 2 * t;
        reinterpret_cast<uint32_t*>(smem + OFF_B2H)[idx] = pk16(b2[n0], b2[n0 + 1]);
        reinterpret_cast<float2*>(smem + OFF_W3F)[idx] = make_float2(W3[n0], W3[n0 + 1]);
    }
    // ---- small weights ----
    {
        float4* w1v  = reinterpret_cast<float4*>(smem + OFF_W1);
        float2* bwv2 = reinterpret_cast<float2*>(smem + OFF_BW);
        float4* r1av = reinterpret_cast<float4*>(smem + OFF_R1A);
        float4* r1bv = reinterpret_cast<float4*>(smem + OFF_R1B);
        float4* r2v  = reinterpret_cast<float4*>(smem + OFF_R2);
        for (int j = tid; j < HN; j += 128) {
            w1v[j]  = make_float4(W1[j], W1[HN + j], W1[2 * HN + j], b1[j]);
            bwv2[j] = make_float2(b2[j], W3[j]);
            r1av[j] = make_float4(R1[j], R1[HN + j], R1[2 * HN + j], R1[3 * HN + j]);
            r1bv[j] = make_float4(R1[4 * HN + j], R1[5 * HN + j], rb1[j], 0.0f);
            r2v[j]  = make_float4(R2[3 * j], R2[3 * j + 1], R2[3 * j + 2], 0.0f);
        }
    }
    if (tid < 3) smem[OFF_MISC + tid] = rb2[tid];
    if (tid == 0) smem[OFF_MISC + 3] = b3[0];
    __syncthreads();

    const float4* w1pack   = reinterpret_cast<const float4*>(smem + OFF_W1);
    const float4* w1b      = reinterpret_cast<const float4*>(smem + OFF_W1B);
    const float4* sBH      = reinterpret_cast<const float4*>(smem + OFF_BH);
    const float4* bwv      = reinterpret_cast<const float4*>(smem + OFF_BW);
    const uint32_t* b2h    = reinterpret_cast<const uint32_t*>(smem + OFF_B2H);
    const float2*  w3f     = reinterpret_cast<const float2*>(smem + OFF_W3F);
    const float bb3 = smem[OFF_MISC + 3];

    int ray = blockIdx.x * 128 + tid;
    const bool active = ray < n;
    if (!active) ray = n - 1;
    const float ro0 = rays[ray * 6 + 0], ro1 = rays[ray * 6 + 1], ro2 = rays[ray * 6 + 2];
    const float rd0 = rays[ray * 6 + 3], rd1 = rays[ray * 6 + 4], rd2 = rays[ray * 6 + 5];

    // ============ sphere tracing (warp-wide early break) ============
    float cd = kNEAR;
    bool hit = false;
#pragma unroll 1
    for (int it = 0; it < kITERS; ++it) {
        float x0 = __fadd_rn(ro0, __fmul_rn(rd0, cd));
        float x1 = __fadd_rn(ro1, __fmul_rn(rd1, cd));
        float x2 = __fadd_rn(ro2, __fmul_rn(rd2, cd));
        float dist = sdf_approx(x0, x1, x2, w1b, sBH, b2h, w3f, lane) + bb3;
        bool h = (dist < kEPS) && (cd >= kNEAR) && (cd <= kFAR);
        hit = hit || h;
        if (!hit) cd += dist;
        if (__all_sync(0xffffffffu, hit)) break;
    }

    // ============ reflectance MLP (scalar, cheap) ============
    float p0 = __fadd_rn(ro0, __fmul_rn(rd0, cd));
    float p1 = __fadd_rn(ro1, __fmul_rn(rd1, cd));
    float p2 = __fadd_rn(ro2, __fmul_rn(rd2, cd));
    float rgb0 = smem[OFF_MISC + 0], rgb1 = smem[OFF_MISC + 1], rgb2 = smem[OFF_MISC + 2];
    {
        const float4* r1a = reinterpret_cast<const float4*>(smem + OFF_R1A);
        const float4* r1b = reinterpret_cast<const float4*>(smem + OFF_R1B);
        const float4* r2v = reinterpret_cast<const float4*>(smem + OFF_R2);
#pragma unroll 4
        for (int j = 0; j < HN; ++j) {
            float4 a = r1a[j];
            float4 b = r1b[j];
            float hv = fmaf(a.x, p0, fmaf(a.y, p1, fmaf(a.z, p2,
                       fmaf(a.w, rd0, fmaf(b.x, rd1, fmaf(b.y, rd2, b.z))))));
            hv = fmaxf(hv, 0.0f);
            float4 w = r2v[j];
            rgb0 = fmaf(hv, w.x, rgb0);
            rgb1 = fmaf(hv, w.y, rgb1);
            rgb2 = fmaf(hv, w.z, rgb2);
        }
    }
    if (!hit) { rgb0 = 0.0f; rgb1 = 0.0f; rgb2 = 0.0f; }

    // ============ tube-point scan (approx ranking) ============
    float m_ap = __int_as_float(0x7f800000);
    int   bi   = 0;
#pragma unroll 1
    for (int i = 0; i <= kTP; ++i) {
        float t = kSTEP * (float)i;
        float x0 = __fadd_rn(ro0, __fmul_rn(rd0, t));
        float x1 = __fadd_rn(ro1, __fmul_rn(rd1, t));
        float x2 = __fadd_rn(ro2, __fmul_rn(rd2, t));
        float sd = sdf_approx(x0, x1, x2, w1b, sBH, b2h, w3f, lane);
        if (sd < m_ap) { m_ap = sd; bi = i; }
    }
    // precise re-eval at the per-ray argmin point (tput == curr_min identity)
    float m;
    {
        float tb = kSTEP * (float)bi;
        float x0 = __fadd_rn(ro0, __fmul_rn(rd0, tb));
        float x1 = __fadd_rn(ro1, __fmul_rn(rd1, tb));
        float x2 = __fadd_rn(ro2, __fmul_rn(rd2, tb));
        float X0[4], X1[4], X2[4];
        bcast_X(x0, x1, x2, lane, X0, X1, X2);
        m = sdf_precise(X0, X1, X2, w1pack, sBH, bwv, lane) + bb3;
    }

    if (active) {
        float4 o;
        o.x = rgb0; o.y = rgb1; o.z = rgb2; o.w = -kALPHA * m;
        reinterpret_cast<float4*>(out)[ray] = o;
    }
}

extern "C" void kernel_launch(void* const* d_in, const int* in_sizes, int n_in,
                              void* d_out, int out_size) {
    const float* rays = (const float*)d_in[0];
    const float* W1   = (const float*)d_in[1];
    const float* b1   = (const float*)d_in[2];
    const float* W2   = (const float*)d_in[3];
    const float* b2   = (const float*)d_in[4];
    const float* W3   = (const float*)d_in[5];
    const float* b3   = (const float*)d_in[6];
    const float* R1   = (const float*)d_in[7];
    const float* rb1  = (const float*)d_in[8];
    const float* R2   = (const float*)d_in[9];
    const float* rb2  = (const float*)d_in[10];
    float* out = (float*)d_out;

    const int n = in_sizes[0] / 6;

    sdf_prep_kernel<<<16, 128>>>(W2);

    cudaFuncSetAttribute(sdf_mma_kernel,
                         cudaFuncAttributeMaxDynamicSharedMemorySize, SMEM_BYTES);

    const int grid = (n + 127) / 128;
    sdf_mma_kernel<<<grid, 128, SMEM_BYTES>>>(
        rays, W1, b1, W2, b2, W3, b3, R1, rb1, R2, rb2, out, n);
}